// round 11
// baseline (speedup 1.0000x reference)
#include <cuda_runtime.h>
#include <math.h>

#define SOSID 2
#define EPSF  1e-6f

typedef unsigned long long u64;

// ---------------- persistent device state ----------------
__device__ float g_phi_hs[3200*512];
__device__ float g_phi_fds[3200*512];
__device__ float g_zx[2080*2048];
__device__ float g_encT[32*512*104];
__device__ float g_hbuf[2][32*512];
__device__ float g_cbuf[2][32*512];
__device__ float g_ot[32*512];
__device__ float g_gamma[32*512];
__device__ float g_alpha[32*512];
__device__ float g_ctx[32*512];
__device__ float g_att[2][32*512];     // double-buffered by t&1 (logits overlaps next chain)
__device__ float g_WsT[512*512];
__device__ float g_WrT[512*512];
__device__ float g_WoT[512*1024];

// ---------------- helpers ----------------
__device__ __forceinline__ u64 pk2(float lo, float hi){
    u64 r; asm("mov.b64 %0, {%1,%2};" : "=l"(r) : "f"(lo), "f"(hi)); return r;
}
__device__ __forceinline__ void upk2(u64 v, float& lo, float& hi){
    asm("mov.b64 {%0,%1}, %2;" : "=f"(lo), "=f"(hi) : "l"(v));
}
__device__ __forceinline__ u64 ffma2(u64 a, u64 b, u64 c){
    u64 r; asm("fma.rn.f32x2 %0, %1, %2, %3;" : "=l"(r) : "l"(a), "l"(b), "l"(c)); return r;
}
__device__ __forceinline__ u64 fadd2(u64 a, u64 b){
    u64 r; asm("add.rn.f32x2 %0, %1, %2;" : "=l"(r) : "l"(a), "l"(b)); return r;
}
__device__ __forceinline__ float sigf(float x){ return 1.f/(1.f+expf(-x)); }

// ---------------- pipelined inner-loop building blocks ----------------
__device__ __forceinline__ void load4v(float4 (&w)[4], const float*& wp, int ldw){
    #pragma unroll
    for (int i=0;i<4;i++){ w[i] = *(const float4*)wp; wp += ldw; }
}
__device__ __forceinline__ void comp4v(u64 (&acc)[8][4], const float*& ap, const float4 (&w)[4]){
    #pragma unroll
    for (int i=0;i<4;i++){
        u64 b0=pk2(w[i].x,w[i].x), b1=pk2(w[i].y,w[i].y),
            b2=pk2(w[i].z,w[i].z), b3=pk2(w[i].w,w[i].w);
        u64 aa[8];
        #pragma unroll
        for (int m=0;m<8;m++) aa[m]=((const u64*)ap)[m];
        ap += 36;
        #pragma unroll
        for (int m=0;m<8;m++){
            acc[m][0]=ffma2(aa[m],b0,acc[m][0]);
            acc[m][1]=ffma2(aa[m],b1,acc[m][1]);
            acc[m][2]=ffma2(aa[m],b2,acc[m][2]);
            acc[m][3]=ffma2(aa[m],b3,acc[m][3]);
        }
    }
}
__device__ __forceinline__ void load4g(float (&w)[16], const float*& wp){
    #pragma unroll
    for (int i=0;i<4;i++){
        w[i*4+0]=wp[0]; w[i*4+1]=wp[512]; w[i*4+2]=wp[1024]; w[i*4+3]=wp[1536];
        wp += 2048;
    }
}
__device__ __forceinline__ void comp4gb(u64 (&acc)[4][4], const float*& ap, const float (&w)[16]){
    #pragma unroll
    for (int i=0;i<4;i++){
        u64 b0=pk2(w[i*4+0],w[i*4+0]), b1=pk2(w[i*4+1],w[i*4+1]),
            b2=pk2(w[i*4+2],w[i*4+2]), b3=pk2(w[i*4+3],w[i*4+3]);
        u64 a0=((const u64*)ap)[0], a1=((const u64*)ap)[1],
            a2=((const u64*)ap)[2], a3=((const u64*)ap)[3];
        ap += 36;
        acc[0][0]=ffma2(a0,b0,acc[0][0]); acc[1][0]=ffma2(a1,b0,acc[1][0]);
        acc[2][0]=ffma2(a2,b0,acc[2][0]); acc[3][0]=ffma2(a3,b0,acc[3][0]);
        acc[0][1]=ffma2(a0,b1,acc[0][1]); acc[1][1]=ffma2(a1,b1,acc[1][1]);
        acc[2][1]=ffma2(a2,b1,acc[2][1]); acc[3][1]=ffma2(a3,b1,acc[3][1]);
        acc[0][2]=ffma2(a0,b2,acc[0][2]); acc[1][2]=ffma2(a1,b2,acc[1][2]);
        acc[2][2]=ffma2(a2,b2,acc[2][2]); acc[3][2]=ffma2(a3,b2,acc[3][2]);
        acc[0][3]=ffma2(a0,b3,acc[0][3]); acc[1][3]=ffma2(a1,b3,acc[1][3]);
        acc[2][3]=ffma2(a2,b3,acc[2][3]); acc[3][3]=ffma2(a3,b3,acc[3][3]);
    }
}

// ================= precompute GEMM (device fn, reduction aliased on A-tile) ====
// 256 threads: cg=tid&63 (4 cols), rh=(tid>>6)&1, ks=tid>>7 (2-way K split)
template<int K, int AMODE, int EPI>
__device__ void dev_g32(float* sm,
    const float* __restrict__ W, const float* __restrict__ Bv,
    const float* __restrict__ A, int lda, int ldw,
    const float* __restrict__ p1, int rowBase, int tt, int colblk)
{
    const int tid = threadIdx.x;
    const int cg  = tid & 63;
    const int rh  = (tid >> 6) & 1;
    const int ks  = tid >> 7;

    for (int idx = tid; idx < 32*K; idx += 256){
        int m = idx / K, k = idx - m*K;
        float v;
        if (AMODE==0) v = A[(size_t)(rowBase+m)*lda + k];
        else          v = (tt==0) ? A[SOSID*512 + k]
                                  : p1[((size_t)m*64 + (tt-1))*512 + k];
        sm[k*36 + m] = v;
    }
    __syncthreads();

    u64 acc[8][4];
    #pragma unroll
    for (int i=0;i<8;i++){ acc[i][0]=0; acc[i][1]=0; acc[i][2]=0; acc[i][3]=0; }

    const float* wp = W + (size_t)(ks*(K/2))*ldw + colblk*256 + cg*4;
    const float* ap = sm + (ks*(K/2))*36 + rh*16;
    const int NT2 = ((K/2)/4)/2;

    float4 wa[4], wb[4];
    load4v(wa, wp, ldw);
    #pragma unroll 1
    for (int j=0;j<NT2-1;j++){
        load4v(wb, wp, ldw);
        comp4v(acc, ap, wa);
        load4v(wa, wp, ldw);
        comp4v(acc, ap, wb);
    }
    load4v(wb, wp, ldw);
    comp4v(acc, ap, wa);
    comp4v(acc, ap, wb);

    __syncthreads();                         // all A-tile reads done
    u64* red = (u64*)sm;                     // alias reduction over A-tile
    u64* mr  = red + (size_t)tid*33;
    #pragma unroll
    for (int m2=0;m2<8;m2++){
        mr[4*m2+0]=acc[m2][0]; mr[4*m2+1]=acc[m2][1];
        mr[4*m2+2]=acc[m2][2]; mr[4*m2+3]=acc[m2][3];
    }
    __syncthreads();
    if (ks == 0){
        const u64* pr = red + (size_t)(tid + 128)*33;
        #pragma unroll
        for (int m2=0;m2<8;m2++){
            acc[m2][0]=fadd2(acc[m2][0],pr[4*m2+0]);
            acc[m2][1]=fadd2(acc[m2][1],pr[4*m2+1]);
            acc[m2][2]=fadd2(acc[m2][2],pr[4*m2+2]);
            acc[m2][3]=fadd2(acc[m2][3],pr[4*m2+3]);
        }
        int c0 = colblk*256 + cg*4;
        #pragma unroll
        for (int m2=0;m2<8;m2++){
            float v0[4], v1[4];
            upk2(acc[m2][0],v0[0],v1[0]); upk2(acc[m2][1],v0[1],v1[1]);
            upk2(acc[m2][2],v0[2],v1[2]); upk2(acc[m2][3],v0[3],v1[3]);
            #pragma unroll
            for (int r=0;r<2;r++){
                int row = rowBase + rh*16 + 2*m2 + r;
                const float* vv = r ? v1 : v0;
                #pragma unroll
                for (int j=0;j<4;j++){
                    int c = c0 + j;
                    float x = vv[j] + Bv[c];
                    if (EPI==0)      g_phi_hs [(size_t)row*512 +c] = tanhf(x);
                    else if (EPI==1) g_phi_fds[(size_t)row*512 +c] = tanhf(x);
                    else             g_zx     [(size_t)row*2048+c] = x;
                }
            }
        }
    }
}

// ---- pre_all: transposes + h/c init + all precompute GEMMs in ONE launch ----
__global__ void __launch_bounds__(256)
pre_all(const float* __restrict__ h0,  const float* __restrict__ c0,
        const float* __restrict__ enc, const float* __restrict__ fld,
        const float* __restrict__ emb, const float* __restrict__ inp,
        const float* __restrict__ lW,  const float* __restrict__ lb,
        const float* __restrict__ Wh,  const float* __restrict__ bh,
        const float* __restrict__ Wf,  const float* __restrict__ bf,
        const float* __restrict__ Ws,  const float* __restrict__ Wr,
        const float* __restrict__ Wo)
{
    extern __shared__ float sm[];
    const int task = blockIdx.x;
    const int tid  = threadIdx.x;

    if (task < 200){
        dev_g32<512,0,0>(sm, Wh, bh, enc, 512, 512, nullptr, (task>>1)*32, 0, task&1);
    } else if (task < 400){
        int x = task - 200;
        dev_g32<64,0,1>(sm, Wf, bf, fld, 64, 512, nullptr, (x>>1)*32, 0, x&1);
    } else if (task < 920){
        int x = task - 400;
        dev_g32<512,1,2>(sm, lW, lb, emb, 512, 2048, inp, (x>>3)*32, x>>3, x&7);
    } else {
        const int gt = (task-920)*256 + tid, gs = 80*256;
        for (int i=gt; i<16384; i+=gs){ g_hbuf[0][i]=h0[i]; g_cbuf[0][i]=c0[i]; }
        for (int i=gt; i<512*512; i+=gs){
            int c=i>>9, k=i&511;
            g_WsT[i] = Ws[(size_t)k*512+c];
            g_WrT[i] = Wr[(size_t)k*512+c];
        }
        for (int i=gt; i<512*1024; i+=gs){
            int c=i>>10, k=i&1023;
            g_WoT[i] = Wo[(size_t)k*512+c];
        }
        for (int i=gt; i<32*512*104; i+=gs){
            int l=i%104; int hh=(i/104)&511; int b=i/(104*512);
            g_encT[i] = (l<100) ? enc[((size_t)b*100+l)*512+hh] : 0.f;
        }
    }
}

// ================= per-step kernels =================

// ---- LSTM: grid 64 x 256; 8 h-cols/block; 8-way K-split ----
__global__ void __launch_bounds__(256)
lstm_k(const float* __restrict__ lWh, const int* __restrict__ lens, int t)
{
    extern __shared__ float sm[];
    const int tid = threadIdx.x, blk = blockIdx.x;
    const int pb = t & 1, cb = pb ^ 1;
    const int hbase = blk * 8;

    for (int idx = tid; idx < 32*512; idx += 256){
        int m = idx >> 9, k = idx & 511;
        sm[k*36 + m] = g_hbuf[pb][m*512 + k];
    }
    __syncthreads();

    const int cg = tid & 7;
    const int rg = (tid >> 3) & 3;
    const int ks = tid >> 5;

    u64 acc[4][4];
    #pragma unroll
    for (int i=0;i<4;i++){ acc[i][0]=0; acc[i][1]=0; acc[i][2]=0; acc[i][3]=0; }

    const float* wp = lWh + (size_t)(ks*64)*2048 + hbase + cg;
    const float* ap = sm + (ks*64)*36 + rg*8;

    float wa[16], wb[16];
    load4g(wa, wp);
    #pragma unroll 1
    for (int j=0;j<7;j++){
        load4g(wb, wp);
        comp4gb(acc, ap, wa);
        load4g(wa, wp);
        comp4gb(acc, ap, wb);
    }
    load4g(wb, wp);
    comp4gb(acc, ap, wa);
    comp4gb(acc, ap, wb);

    __syncthreads();
    u64* red = (u64*)sm;
    u64* mr  = red + (size_t)tid*16;
    #pragma unroll
    for (int p=0;p<4;p++){
        mr[4*p+0]=acc[p][0]; mr[4*p+1]=acc[p][1];
        mr[4*p+2]=acc[p][2]; mr[4*p+3]=acc[p][3];
    }
    __syncthreads();
    for (int s=4; s>=1; s>>=1){
        if (ks < s){
            const u64* pr = red + (size_t)(tid + s*32)*16;
            #pragma unroll
            for (int p=0;p<4;p++){
                acc[p][0]=fadd2(acc[p][0],pr[4*p+0]);
                acc[p][1]=fadd2(acc[p][1],pr[4*p+1]);
                acc[p][2]=fadd2(acc[p][2],pr[4*p+2]);
                acc[p][3]=fadd2(acc[p][3],pr[4*p+3]);
            }
            if (s>1){
                #pragma unroll
                for (int p=0;p<4;p++){
                    mr[4*p+0]=acc[p][0]; mr[4*p+1]=acc[p][1];
                    mr[4*p+2]=acc[p][2]; mr[4*p+3]=acc[p][3];
                }
            }
        }
        __syncthreads();
    }

    if (ks == 0){
        const int h = hbase + cg;
        #pragma unroll
        for (int p=0;p<4;p++){
            float zi[2],zj[2],zf[2],zo[2];
            upk2(acc[p][0],zi[0],zi[1]); upk2(acc[p][1],zj[0],zj[1]);
            upk2(acc[p][2],zf[0],zf[1]); upk2(acc[p][3],zo[0],zo[1]);
            #pragma unroll
            for (int r=0;r<2;r++){
                int b = rg*8 + 2*p + r;
                const float* zxp = g_zx + ((size_t)(t*32+b))*2048 + h;
                float vi = zi[r] + zxp[0];
                float vj = zj[r] + zxp[512];
                float vf = zf[r] + zxp[1024];
                float vo = zo[r] + zxp[1536];
                float cp = g_cbuf[pb][b*512+h];
                float hp = g_hbuf[pb][b*512+h];
                float cn = sigf(vf+1.f)*cp + sigf(vi)*tanhf(vj);
                float hn = sigf(vo)*tanhf(cn);
                bool fin = (t>0) && (t-1 >= lens[b]);
                g_ot[b*512+h]       = fin ? 0.f : hn;
                g_hbuf[cb][b*512+h] = fin ? hp  : hn;
                g_cbuf[cb][b*512+h] = fin ? cp  : cn;
            }
        }
    }
}

// ---- gamma/alpha: grid 128 x 256, warp per column ----
__global__ void __launch_bounds__(256)
gam_k(const float* __restrict__ bs, const float* __restrict__ br)
{
    extern __shared__ float sm[];
    float* at2 = sm;
    float* wst = sm + 512*33;
    const int tid = threadIdx.x, blk = blockIdx.x;
    const int warp = tid >> 5, lane = tid & 31;

    for (int idx = tid; idx < 32*512; idx += 256){
        int m = idx >> 9, k = idx & 511;
        at2[k*33 + m] = g_ot[m*512 + k];
    }
    const float* WT = (blk < 64) ? g_WsT : g_WrT;
    const int c0 = (blk & 63) * 8;
    for (int idx = tid; idx < 8*512; idx += 256){
        int w = idx >> 9, k = idx & 511;
        wst[w*520 + k] = WT[(size_t)(c0+w)*512 + k];
    }
    __syncthreads();

    const int c = c0 + warp;
    const float* a  = at2 + lane;
    const float* wr = wst + warp*520;
    float a0=0.f,a1=0.f,a2=0.f,a3=0.f;
    #pragma unroll 4
    for (int k=0;k<512;k+=4){
        a0 = fmaf(a[(k+0)*33], wr[k+0], a0);
        a1 = fmaf(a[(k+1)*33], wr[k+1], a1);
        a2 = fmaf(a[(k+2)*33], wr[k+2], a2);
        a3 = fmaf(a[(k+3)*33], wr[k+3], a3);
    }
    float s = (a0+a1)+(a2+a3);
    float v = tanhf(s + ((blk<64)? bs[c] : br[c]));
    float* dst = (blk<64)? g_gamma : g_alpha;
    dst[lane*512 + c] = v;
}

// ---- attention: grid 32 x 256 ----
__global__ void __launch_bounds__(256)
attn_k()
{
    __shared__ float sg[512], sa[512], sh_[100], sf_[100], sw_[104], aux[3];
    const int b = blockIdx.x;
    const int tid = threadIdx.x, warp = tid >> 5, lane = tid & 31;

    for (int i = tid; i < 512; i += 256){
        sg[i] = g_gamma[b*512+i];
        sa[i] = g_alpha[b*512+i];
    }
    __syncthreads();

    for (int l = warp; l < 100; l += 8){
        const float* ph = g_phi_hs  + ((size_t)b*100 + l)*512;
        const float* pf = g_phi_fds + ((size_t)b*100 + l)*512;
        float s1=0.f, s2=0.f;
        for (int k=lane; k<512; k+=32){ s1 += ph[k]*sg[k]; s2 += pf[k]*sa[k]; }
        #pragma unroll
        for (int o=16;o;o>>=1){ s1 += __shfl_xor_sync(~0u,s1,o); s2 += __shfl_xor_sync(~0u,s2,o); }
        if (lane==0){ sh_[l]=s1; sf_[l]=s2; }
    }
    __syncthreads();

    if (warp < 2){
        float* s = warp ? sf_ : sh_;
        float mx = -1e30f;
        for (int l=lane;l<100;l+=32) mx = fmaxf(mx, s[l]);
        #pragma unroll
        for (int o=16;o;o>>=1) mx = fmaxf(mx, __shfl_xor_sync(~0u,mx,o));
        float sum = 0.f;
        for (int l=lane;l<100;l+=32){ float e = expf(s[l]-mx); s[l]=e; sum+=e; }
        #pragma unroll
        for (int o=16;o;o>>=1) sum += __shfl_xor_sync(~0u,sum,o);
        if (lane==0) aux[warp] = EPSF + sum;
    }
    __syncthreads();

    if (warp == 0){
        float d1 = aux[0], d2 = aux[1];
        float wsum = 0.f;
        for (int l=lane;l<100;l+=32){ float w = (sh_[l]/d1)*(sf_[l]/d2); sw_[l]=w; wsum += w; }
        #pragma unroll
        for (int o=16;o;o>>=1) wsum += __shfl_xor_sync(~0u,wsum,o);
        if (lane==0) aux[2] = EPSF + wsum;
    }
    __syncthreads();
    if (warp == 0){
        float d = aux[2];
        for (int l=lane;l<100;l+=32) sw_[l] = sw_[l]/d;
        if (lane < 4) sw_[100+lane] = 0.f;
    }
    __syncthreads();

    #pragma unroll
    for (int ci=0; ci<2; ci++){
        int h = tid + ci*256;
        const float4* e = (const float4*)(g_encT + ((size_t)b*512 + h)*104);
        float c2 = 0.f;
        #pragma unroll
        for (int l4=0; l4<26; l4++){
            float4 ev = e[l4];
            int l = l4*4;
            c2 += sw_[l+0]*ev.x + sw_[l+1]*ev.y + sw_[l+2]*ev.z + sw_[l+3]*ev.w;
        }
        g_ctx[b*512+h] = c2;
    }
}

// ---- att = tanh([ctx|ot] @ Wo + bo): grid 64 x 256, warp per column ----
__global__ void __launch_bounds__(256)
att_k(const float* __restrict__ bo, const int* __restrict__ lens, int t)
{
    extern __shared__ float sm[];
    float* at4 = sm;
    float* wst = sm + 1024*33;
    const int tid = threadIdx.x, blk = blockIdx.x;
    const int warp = tid >> 5, lane = tid & 31;

    for (int idx = tid; idx < 32*1024; idx += 256){
        int m = idx >> 10, k = idx & 1023;
        float v = (k < 512) ? g_ctx[m*512+k] : g_ot[m*512+k-512];
        at4[k*33 + m] = v;
    }
    const int c0 = blk*8;
    for (int idx = tid; idx < 8*1024; idx += 256){
        int w = idx >> 10, k = idx & 1023;
        wst[w*1040 + k] = g_WoT[(size_t)(c0+w)*1024 + k];
    }
    __syncthreads();

    const int c = c0 + warp;
    const float* a  = at4 + lane;
    const float* wr = wst + warp*1040;
    float a0=0.f,a1=0.f,a2=0.f,a3=0.f;
    #pragma unroll 4
    for (int k=0;k<1024;k+=4){
        a0 = fmaf(a[(k+0)*33], wr[k+0], a0);
        a1 = fmaf(a[(k+1)*33], wr[k+1], a1);
        a2 = fmaf(a[(k+2)*33], wr[k+2], a2);
        a3 = fmaf(a[(k+3)*33], wr[k+3], a3);
    }
    float s = (a0+a1)+(a2+a3);
    float v = tanhf(s + bo[c]);
    bool fin = (t>0) && (t-1 >= lens[lane]);
    g_att[t&1][lane*512 + c] = fin ? 0.f : v;
}

// ---- logits: grid 250 x 256, 128 cols/block, KS=4, 2 blocks/SM ----
__global__ void __launch_bounds__(256)
logits_k(const float* __restrict__ oW, const float* __restrict__ ob,
         const int* __restrict__ lens, float* __restrict__ out, int t)
{
    extern __shared__ float sm[];
    const int tid = threadIdx.x, blk = blockIdx.x;
    const float* attb = g_att[t&1];

    for (int idx = tid; idx < 32*512; idx += 256){
        int m = idx >> 9, k = idx & 511;
        sm[k*36 + m] = attb[m*512 + k];
    }
    __syncthreads();

    const int cg = tid & 31;         // 32 col-groups x 4 cols = 128 cols
    const int rh = (tid >> 5) & 1;
    const int ks = tid >> 6;         // 0..3, 128 k each -> 32 tiles

    u64 acc[8][4];
    #pragma unroll
    for (int i=0;i<8;i++){ acc[i][0]=0; acc[i][1]=0; acc[i][2]=0; acc[i][3]=0; }

    const float* wp = oW + (size_t)(ks*128)*32000 + blk*128 + cg*4;
    const float* ap = sm + (ks*128)*36 + rh*16;

    float4 wa[4], wb[4];
    load4v(wa, wp, 32000);
    #pragma unroll 1
    for (int j=0;j<15;j++){
        load4v(wb, wp, 32000);
        comp4v(acc, ap, wa);
        load4v(wa, wp, 32000);
        comp4v(acc, ap, wb);
    }
    load4v(wb, wp, 32000);
    comp4v(acc, ap, wa);
    comp4v(acc, ap, wb);

    __syncthreads();
    u64* red = (u64*)sm;
    u64* mr  = red + (size_t)tid*33;
    #pragma unroll
    for (int m2=0;m2<8;m2++){
        mr[4*m2+0]=acc[m2][0]; mr[4*m2+1]=acc[m2][1];
        mr[4*m2+2]=acc[m2][2]; mr[4*m2+3]=acc[m2][3];
    }
    __syncthreads();
    for (int s=2; s>=1; s>>=1){
        if (ks < s){
            const u64* pr = red + (size_t)(tid + s*64)*33;
            #pragma unroll
            for (int m2=0;m2<8;m2++){
                acc[m2][0]=fadd2(acc[m2][0],pr[4*m2+0]);
                acc[m2][1]=fadd2(acc[m2][1],pr[4*m2+1]);
                acc[m2][2]=fadd2(acc[m2][2],pr[4*m2+2]);
                acc[m2][3]=fadd2(acc[m2][3],pr[4*m2+3]);
            }
            if (s>1){
                #pragma unroll
                for (int m2=0;m2<8;m2++){
                    mr[4*m2+0]=acc[m2][0]; mr[4*m2+1]=acc[m2][1];
                    mr[4*m2+2]=acc[m2][2]; mr[4*m2+3]=acc[m2][3];
                }
            }
        }
        __syncthreads();
    }
    if (ks == 0){
        const int c0 = blk*128 + cg*4;
        #pragma unroll
        for (int m2=0;m2<8;m2++){
            float v0[4], v1[4];
            upk2(acc[m2][0],v0[0],v1[0]); upk2(acc[m2][1],v0[1],v1[1]);
            upk2(acc[m2][2],v0[2],v1[2]); upk2(acc[m2][3],v0[3],v1[3]);
            #pragma unroll
            for (int r=0;r<2;r++){
                int row = rh*16 + 2*m2 + r;
                bool fin = (t>0) && (t-1 >= lens[row]);
                const float* vv = r ? v1 : v0;
                float* op = out + (size_t)row*2080000 + (size_t)t*32000 + c0;
                #pragma unroll
                for (int j=0;j<4;j++)
                    op[j] = fin ? 0.f : (vv[j] + ob[c0+j]);
            }
        }
    }
}

// ---- final h/c ----
__global__ void fin_k(float* __restrict__ out)
{
    int i = blockIdx.x*256 + threadIdx.x;
    if (i < 16384){
        out[66560000 + i]         = g_hbuf[1][i];
        out[66560000 + 16384 + i] = g_cbuf[1][i];
    }
}

// ---------------- host ----------------
extern "C" void kernel_launch(void* const* d_in, const int* in_sizes, int n_in,
                              void* d_out, int out_size)
{
    const float* h0   = (const float*)d_in[0];
    const float* c0   = (const float*)d_in[1];
    const float* inp  = (const float*)d_in[2];
    const float* enc  = (const float*)d_in[3];
    const float* fld  = (const float*)d_in[4];
    const float* emb  = (const float*)d_in[5];
    const float* lW   = (const float*)d_in[6];
    const float* lb   = (const float*)d_in[7];
    const float* Wh   = (const float*)d_in[8];
    const float* bh   = (const float*)d_in[9];
    const float* Ws   = (const float*)d_in[10];
    const float* bs   = (const float*)d_in[11];
    const float* Wr   = (const float*)d_in[12];
    const float* br   = (const float*)d_in[13];
    const float* Wf   = (const float*)d_in[14];
    const float* bf   = (const float*)d_in[15];
    const float* Wo   = (const float*)d_in[16];
    const float* bo   = (const float*)d_in[17];
    const float* oW   = (const float*)d_in[18];
    const float* ob   = (const float*)d_in[19];
    const int*   lens = (const int*)  d_in[20];
    float* out = (float*)d_out;

    const int SM_PRE  = 512*36*4;               // 73728 (reduction aliased)
    const int SM_LSTM = 512*36*4;               // 73728
    const int SM_GAM  = 512*33*4 + 8*520*4;     // 84224
    const int SM_ATT  = 1024*33*4 + 8*1040*4;   // 168448
    const int SM_LOG  = 512*36*4;               // 73728 (2 blocks/SM)

    cudaFuncSetAttribute((const void*)pre_all,  cudaFuncAttributeMaxDynamicSharedMemorySize, SM_PRE);
    cudaFuncSetAttribute((const void*)lstm_k,   cudaFuncAttributeMaxDynamicSharedMemorySize, SM_LSTM);
    cudaFuncSetAttribute((const void*)gam_k,    cudaFuncAttributeMaxDynamicSharedMemorySize, SM_GAM);
    cudaFuncSetAttribute((const void*)att_k,    cudaFuncAttributeMaxDynamicSharedMemorySize, SM_ATT);
    cudaFuncSetAttribute((const void*)logits_k, cudaFuncAttributeMaxDynamicSharedMemorySize, SM_LOG);

    // fork stream + events for chain/logits overlap (created per call; host-side only)
    cudaStream_t s2;
    cudaStreamCreateWithFlags(&s2, cudaStreamNonBlocking);
    cudaEvent_t eA, eB0, eB1;
    cudaEventCreateWithFlags(&eA,  cudaEventDisableTiming);
    cudaEventCreateWithFlags(&eB0, cudaEventDisableTiming);
    cudaEventCreateWithFlags(&eB1, cudaEventDisableTiming);

    // launch 0: all precompute in one kernel (ncu -s 5 then lands on logits_k)
    pre_all<<<1000, 256, SM_PRE>>>(h0, c0, enc, fld, emb, inp, lW, lb,
                                   Wh, bh, Wf, bf, Ws, Wr, Wo);

    const float* lWh = lW + (size_t)512*2048;
    for (int t = 0; t < 65; t++){
        // WAR guard: att_k(t) rewrites g_att[t&1], read by logits(t-2)
        if (t >= 2) cudaStreamWaitEvent(0, (t&1) ? eB1 : eB0, 0);

        lstm_k<<<64, 256, SM_LSTM>>>(lWh, lens, t);
        gam_k <<<128,256, SM_GAM >>>(bs, br);
        attn_k<<<32, 256>>>();
        att_k <<<64, 256, SM_ATT >>>(bo, lens, t);

        cudaEventRecord(eA, 0);
        cudaStreamWaitEvent(s2, eA, 0);
        logits_k<<<250, 256, SM_LOG, s2>>>(oW, ob, lens, out, t);
        cudaEventRecord((t&1) ? eB1 : eB0, s2);
    }
    // join logits stream back before final state write
    cudaStreamWaitEvent(0, eB0, 0);
    cudaStreamWaitEvent(0, eB1, 0);
    fin_k<<<64, 256>>>(out);

    (void)in_sizes; (void)n_in; (void)out_size;
}

// round 12
// speedup vs baseline: 1.2082x; 1.2082x over previous
#include <cuda_runtime.h>
#include <math.h>

#define SOSID 2
#define EPSF  1e-6f

typedef unsigned long long u64;

// ---------------- persistent device state ----------------
__device__ float g_phi_hs[3200*512];
__device__ float g_phi_fds[3200*512];
__device__ float g_zx[2080*2048];
__device__ float g_encT[32*512*104];
__device__ float g_hbuf[2][32*512];
__device__ float g_cbuf[2][32*512];
__device__ float g_ot[32*512];
__device__ float g_gamma[32*512];
__device__ float g_alpha[32*512];
__device__ float g_ctx[32*512];
__device__ float g_att[2][32*512];     // double-buffered by t&1
__device__ float g_sch[3200];          // attention scores (h)
__device__ float g_scf[3200];          // attention scores (f)
__device__ int          g_cnt;
__device__ volatile int g_gen;

// ---------------- helpers ----------------
__device__ __forceinline__ u64 pk2(float lo, float hi){
    u64 r; asm("mov.b64 %0, {%1,%2};" : "=l"(r) : "f"(lo), "f"(hi)); return r;
}
__device__ __forceinline__ void upk2(u64 v, float& lo, float& hi){
    asm("mov.b64 {%0,%1}, %2;" : "=f"(lo), "=f"(hi) : "l"(v));
}
__device__ __forceinline__ u64 ffma2(u64 a, u64 b, u64 c){
    u64 r; asm("fma.rn.f32x2 %0, %1, %2, %3;" : "=l"(r) : "l"(a), "l"(b), "l"(c)); return r;
}
__device__ __forceinline__ u64 fadd2(u64 a, u64 b){
    u64 r; asm("add.rn.f32x2 %0, %1, %2;" : "=l"(r) : "l"(a), "l"(b)); return r;
}
__device__ __forceinline__ float sigf(float x){ return 1.f/(1.f+expf(-x)); }

// global barrier for the fused chain kernel (gridDim.x blocks)
__device__ __forceinline__ void gsync(){
    __threadfence();
    __syncthreads();
    if (threadIdx.x == 0){
        int g = g_gen;
        if (atomicAdd(&g_cnt, 1) == (int)gridDim.x - 1){
            g_cnt = 0;
            __threadfence();
            g_gen = g + 1;
        } else {
            while (g_gen == g) { __nanosleep(32); }
        }
    }
    __syncthreads();
}

// ---------------- pipelined inner-loop building blocks ----------------
__device__ __forceinline__ void load4v(float4 (&w)[4], const float*& wp, int ldw){
    #pragma unroll
    for (int i=0;i<4;i++){ w[i] = *(const float4*)wp; wp += ldw; }
}
__device__ __forceinline__ void comp4v(u64 (&acc)[8][4], const float*& ap, const float4 (&w)[4]){
    #pragma unroll
    for (int i=0;i<4;i++){
        u64 b0=pk2(w[i].x,w[i].x), b1=pk2(w[i].y,w[i].y),
            b2=pk2(w[i].z,w[i].z), b3=pk2(w[i].w,w[i].w);
        u64 aa[8];
        #pragma unroll
        for (int m=0;m<8;m++) aa[m]=((const u64*)ap)[m];
        ap += 36;
        #pragma unroll
        for (int m=0;m<8;m++){
            acc[m][0]=ffma2(aa[m],b0,acc[m][0]);
            acc[m][1]=ffma2(aa[m],b1,acc[m][1]);
            acc[m][2]=ffma2(aa[m],b2,acc[m][2]);
            acc[m][3]=ffma2(aa[m],b3,acc[m][3]);
        }
    }
}
__device__ __forceinline__ void load4g(float (&w)[16], const float*& wp){
    #pragma unroll
    for (int i=0;i<4;i++){
        w[i*4+0]=wp[0]; w[i*4+1]=wp[512]; w[i*4+2]=wp[1024]; w[i*4+3]=wp[1536];
        wp += 2048;
    }
}
__device__ __forceinline__ void comp4gb(u64 (&acc)[4][4], const float*& ap, const float (&w)[16]){
    #pragma unroll
    for (int i=0;i<4;i++){
        u64 b0=pk2(w[i*4+0],w[i*4+0]), b1=pk2(w[i*4+1],w[i*4+1]),
            b2=pk2(w[i*4+2],w[i*4+2]), b3=pk2(w[i*4+3],w[i*4+3]);
        u64 a0=((const u64*)ap)[0], a1=((const u64*)ap)[1],
            a2=((const u64*)ap)[2], a3=((const u64*)ap)[3];
        ap += 36;
        acc[0][0]=ffma2(a0,b0,acc[0][0]); acc[1][0]=ffma2(a1,b0,acc[1][0]);
        acc[2][0]=ffma2(a2,b0,acc[2][0]); acc[3][0]=ffma2(a3,b0,acc[3][0]);
        acc[0][1]=ffma2(a0,b1,acc[0][1]); acc[1][1]=ffma2(a1,b1,acc[1][1]);
        acc[2][1]=ffma2(a2,b1,acc[2][1]); acc[3][1]=ffma2(a3,b1,acc[3][1]);
        acc[0][2]=ffma2(a0,b2,acc[0][2]); acc[1][2]=ffma2(a1,b2,acc[1][2]);
        acc[2][2]=ffma2(a2,b2,acc[2][2]); acc[3][2]=ffma2(a3,b2,acc[3][2]);
        acc[0][3]=ffma2(a0,b3,acc[0][3]); acc[1][3]=ffma2(a1,b3,acc[1][3]);
        acc[2][3]=ffma2(a2,b3,acc[2][3]); acc[3][3]=ffma2(a3,b3,acc[3][3]);
    }
}

// small-N f32x2 GEMM phase: 32 cols/block, tree-reduced K split (16-way)
// at = staged A^T [K x 36]; returns acc in ks==0 threads
template<int KSPLIT, int KTOT>
__device__ __forceinline__ bool gemm32(float* sm, const float* __restrict__ W,
                                       int colbase, u64 (&acc)[8][4])
{
    const int tid = threadIdx.x;
    const int cg = tid & 7;
    const int rh = (tid >> 3) & 1;
    const int ks = tid >> 4;
    constexpr int KPER = KTOT / KSPLIT;       // k per split
    constexpr int NT2  = (KPER/4)/2;          // double-buffer pairs

    #pragma unroll
    for (int i=0;i<8;i++){ acc[i][0]=0; acc[i][1]=0; acc[i][2]=0; acc[i][3]=0; }

    const float* wp = W + (size_t)(ks*KPER)*512 + colbase + cg*4;
    const float* ap = sm + (ks*KPER)*36 + rh*16;

    float4 wa[4], wb[4];
    load4v(wa, wp, 512);
    #pragma unroll 1
    for (int j=0;j<NT2-1;j++){
        load4v(wb, wp, 512);
        comp4v(acc, ap, wa);
        load4v(wa, wp, 512);
        comp4v(acc, ap, wb);
    }
    load4v(wb, wp, 512);
    comp4v(acc, ap, wa);
    comp4v(acc, ap, wb);

    __syncthreads();                 // A-tile reads complete -> alias reduction
    u64* red = (u64*)sm;
    u64* mr  = red + (size_t)tid*33;
    #pragma unroll
    for (int m2=0;m2<8;m2++){
        mr[4*m2+0]=acc[m2][0]; mr[4*m2+1]=acc[m2][1];
        mr[4*m2+2]=acc[m2][2]; mr[4*m2+3]=acc[m2][3];
    }
    __syncthreads();
    for (int s=KSPLIT/2; s>=1; s>>=1){
        if (ks < s){
            const u64* pr = red + (size_t)(tid + s*16)*33;
            #pragma unroll
            for (int m2=0;m2<8;m2++){
                acc[m2][0]=fadd2(acc[m2][0],pr[4*m2+0]);
                acc[m2][1]=fadd2(acc[m2][1],pr[4*m2+1]);
                acc[m2][2]=fadd2(acc[m2][2],pr[4*m2+2]);
                acc[m2][3]=fadd2(acc[m2][3],pr[4*m2+3]);
            }
            if (s>1){
                #pragma unroll
                for (int m2=0;m2<8;m2++){
                    mr[4*m2+0]=acc[m2][0]; mr[4*m2+1]=acc[m2][1];
                    mr[4*m2+2]=acc[m2][2]; mr[4*m2+3]=acc[m2][3];
                }
            }
        }
        __syncthreads();
    }
    return ks == 0;
}

// ================= precompute GEMM (device fn, from R10) ====
template<int K, int AMODE, int EPI>
__device__ void dev_g32(float* sm,
    const float* __restrict__ W, const float* __restrict__ Bv,
    const float* __restrict__ A, int lda, int ldw,
    const float* __restrict__ p1, int rowBase, int tt, int colblk)
{
    const int tid = threadIdx.x;
    const int cg  = tid & 63;
    const int rh  = (tid >> 6) & 1;
    const int ks  = tid >> 7;

    for (int idx = tid; idx < 32*K; idx += 256){
        int m = idx / K, k = idx - m*K;
        float v;
        if (AMODE==0) v = A[(size_t)(rowBase+m)*lda + k];
        else          v = (tt==0) ? A[SOSID*512 + k]
                                  : p1[((size_t)m*64 + (tt-1))*512 + k];
        sm[k*36 + m] = v;
    }
    __syncthreads();

    u64 acc[8][4];
    #pragma unroll
    for (int i=0;i<8;i++){ acc[i][0]=0; acc[i][1]=0; acc[i][2]=0; acc[i][3]=0; }

    const float* wp = W + (size_t)(ks*(K/2))*ldw + colblk*256 + cg*4;
    const float* ap = sm + (ks*(K/2))*36 + rh*16;
    const int NT2 = ((K/2)/4)/2;

    float4 wa[4], wb[4];
    load4v(wa, wp, ldw);
    #pragma unroll 1
    for (int j=0;j<NT2-1;j++){
        load4v(wb, wp, ldw);
        comp4v(acc, ap, wa);
        load4v(wa, wp, ldw);
        comp4v(acc, ap, wb);
    }
    load4v(wb, wp, ldw);
    comp4v(acc, ap, wa);
    comp4v(acc, ap, wb);

    __syncthreads();
    u64* red = (u64*)sm;
    u64* mr  = red + (size_t)tid*33;
    #pragma unroll
    for (int m2=0;m2<8;m2++){
        mr[4*m2+0]=acc[m2][0]; mr[4*m2+1]=acc[m2][1];
        mr[4*m2+2]=acc[m2][2]; mr[4*m2+3]=acc[m2][3];
    }
    __syncthreads();
    if (ks == 0){
        const u64* pr = red + (size_t)(tid + 128)*33;
        #pragma unroll
        for (int m2=0;m2<8;m2++){
            acc[m2][0]=fadd2(acc[m2][0],pr[4*m2+0]);
            acc[m2][1]=fadd2(acc[m2][1],pr[4*m2+1]);
            acc[m2][2]=fadd2(acc[m2][2],pr[4*m2+2]);
            acc[m2][3]=fadd2(acc[m2][3],pr[4*m2+3]);
        }
        int c0 = colblk*256 + cg*4;
        #pragma unroll
        for (int m2=0;m2<8;m2++){
            float v0[4], v1[4];
            upk2(acc[m2][0],v0[0],v1[0]); upk2(acc[m2][1],v0[1],v1[1]);
            upk2(acc[m2][2],v0[2],v1[2]); upk2(acc[m2][3],v0[3],v1[3]);
            #pragma unroll
            for (int r=0;r<2;r++){
                int row = rowBase + rh*16 + 2*m2 + r;
                const float* vv = r ? v1 : v0;
                #pragma unroll
                for (int j=0;j<4;j++){
                    int c = c0 + j;
                    float x = vv[j] + Bv[c];
                    if (EPI==0)      g_phi_hs [(size_t)row*512 +c] = tanhf(x);
                    else if (EPI==1) g_phi_fds[(size_t)row*512 +c] = tanhf(x);
                    else             g_zx     [(size_t)row*2048+c] = x;
                }
            }
        }
    }
    __syncthreads();
}

// ---- pre_all: h/c init + encT + all precompute GEMMs in ONE launch ----
__global__ void __launch_bounds__(256)
pre_all(const float* __restrict__ h0,  const float* __restrict__ c0,
        const float* __restrict__ enc, const float* __restrict__ fld,
        const float* __restrict__ emb, const float* __restrict__ inp,
        const float* __restrict__ lW,  const float* __restrict__ lb,
        const float* __restrict__ Wh,  const float* __restrict__ bh,
        const float* __restrict__ Wf,  const float* __restrict__ bf)
{
    extern __shared__ float sm[];
    const int task = blockIdx.x;
    const int tid  = threadIdx.x;

    if (task < 200){
        dev_g32<512,0,0>(sm, Wh, bh, enc, 512, 512, nullptr, (task>>1)*32, 0, task&1);
    } else if (task < 400){
        int x = task - 200;
        dev_g32<64,0,1>(sm, Wf, bf, fld, 64, 512, nullptr, (x>>1)*32, 0, x&1);
    } else if (task < 920){
        int x = task - 400;
        dev_g32<512,1,2>(sm, lW, lb, emb, 512, 2048, inp, (x>>3)*32, x>>3, x&7);
    } else {
        const int gt = (task-920)*256 + tid, gs = 80*256;
        for (int i=gt; i<16384; i+=gs){ g_hbuf[0][i]=h0[i]; g_cbuf[0][i]=c0[i]; }
        for (int i=gt; i<32*512*104; i+=gs){
            int l=i%104; int hh=(i/104)&511; int b=i/(104*512);
            g_encT[i] = (l<100) ? enc[((size_t)b*100+l)*512+hh] : 0.f;
        }
    }
}

__global__ void dummy_k(){}

// ================= fused chain kernel: LSTM -> gam/alpha -> scores -> ctx -> att
__global__ void __launch_bounds__(256, 1)
chain_k(const float* __restrict__ lWh,
        const float* __restrict__ Ws, const float* __restrict__ bs,
        const float* __restrict__ Wr, const float* __restrict__ br,
        const float* __restrict__ Wo, const float* __restrict__ bo,
        const int* __restrict__ lens, int t)
{
    extern __shared__ float sm[];
    const int blk = blockIdx.x;
    const int tid = threadIdx.x;
    const int warp = tid >> 5, lane = tid & 31;

    // ---------- P0: LSTM on blocks 0..63 (8 h-cols each, 8-way K split) ----------
    if (blk < 64){
        const int pb = t & 1, cb = pb ^ 1;
        const int hbase = blk * 8;

        for (int idx = tid; idx < 32*512; idx += 256){
            int m = idx >> 9, k = idx & 511;
            sm[k*36 + m] = g_hbuf[pb][m*512 + k];
        }
        __syncthreads();

        const int cg = tid & 7;
        const int rg = (tid >> 3) & 3;
        const int ks = tid >> 5;

        u64 acc[4][4];
        #pragma unroll
        for (int i=0;i<4;i++){ acc[i][0]=0; acc[i][1]=0; acc[i][2]=0; acc[i][3]=0; }

        const float* wp = lWh + (size_t)(ks*64)*2048 + hbase + cg;
        const float* ap = sm + (ks*64)*36 + rg*8;

        float wa[16], wb[16];
        load4g(wa, wp);
        #pragma unroll 1
        for (int j=0;j<7;j++){
            load4g(wb, wp);
            comp4gb(acc, ap, wa);
            load4g(wa, wp);
            comp4gb(acc, ap, wb);
        }
        load4g(wb, wp);
        comp4gb(acc, ap, wa);
        comp4gb(acc, ap, wb);

        __syncthreads();
        u64* red = (u64*)sm;
        u64* mr  = red + (size_t)tid*16;
        #pragma unroll
        for (int p=0;p<4;p++){
            mr[4*p+0]=acc[p][0]; mr[4*p+1]=acc[p][1];
            mr[4*p+2]=acc[p][2]; mr[4*p+3]=acc[p][3];
        }
        __syncthreads();
        for (int s=4; s>=1; s>>=1){
            if (ks < s){
                const u64* pr = red + (size_t)(tid + s*32)*16;
                #pragma unroll
                for (int p=0;p<4;p++){
                    acc[p][0]=fadd2(acc[p][0],pr[4*p+0]);
                    acc[p][1]=fadd2(acc[p][1],pr[4*p+1]);
                    acc[p][2]=fadd2(acc[p][2],pr[4*p+2]);
                    acc[p][3]=fadd2(acc[p][3],pr[4*p+3]);
                }
                if (s>1){
                    #pragma unroll
                    for (int p=0;p<4;p++){
                        mr[4*p+0]=acc[p][0]; mr[4*p+1]=acc[p][1];
                        mr[4*p+2]=acc[p][2]; mr[4*p+3]=acc[p][3];
                    }
                }
            }
            __syncthreads();
        }

        if (ks == 0){
            const int h = hbase + cg;
            #pragma unroll
            for (int p=0;p<4;p++){
                float zi[2],zj[2],zf[2],zo[2];
                upk2(acc[p][0],zi[0],zi[1]); upk2(acc[p][1],zj[0],zj[1]);
                upk2(acc[p][2],zf[0],zf[1]); upk2(acc[p][3],zo[0],zo[1]);
                #pragma unroll
                for (int r=0;r<2;r++){
                    int b = rg*8 + 2*p + r;
                    const float* zxp = g_zx + ((size_t)(t*32+b))*2048 + h;
                    float vi = zi[r] + zxp[0];
                    float vj = zj[r] + zxp[512];
                    float vf = zf[r] + zxp[1024];
                    float vo = zo[r] + zxp[1536];
                    float cp = g_cbuf[pb][b*512+h];
                    float hp = g_hbuf[pb][b*512+h];
                    float cn = sigf(vf+1.f)*cp + sigf(vi)*tanhf(vj);
                    float hn = sigf(vo)*tanhf(cn);
                    bool fin = (t>0) && (t-1 >= lens[b]);
                    g_ot[b*512+h]       = fin ? 0.f : hn;
                    g_hbuf[cb][b*512+h] = fin ? hp  : hn;
                    g_cbuf[cb][b*512+h] = fin ? cp  : cn;
                }
            }
        }
    }
    gsync();

    // ---------- P1: gamma/alpha on blocks 0..31 (32 cols each, f32x2 GEMM) -------
    if (blk < 32){
        for (int idx = tid; idx < 32*512; idx += 256){
            int m = idx >> 9, k = idx & 511;
            sm[k*36 + m] = g_ot[m*512 + k];
        }
        __syncthreads();
        const float* W  = (blk < 16) ? Ws : Wr;
        const float* Bv = (blk < 16) ? bs : br;
        const int colbase = (blk & 15) * 32;
        u64 acc[8][4];
        if (gemm32<16,512>(sm, W, colbase, acc)){
            const int cg = tid & 7, rh = (tid >> 3) & 1;
            const int c0 = colbase + cg*4;
            float* dst = (blk < 16) ? g_gamma : g_alpha;
            #pragma unroll
            for (int m2=0;m2<8;m2++){
                float v0[4], v1[4];
                upk2(acc[m2][0],v0[0],v1[0]); upk2(acc[m2][1],v0[1],v1[1]);
                upk2(acc[m2][2],v0[2],v1[2]); upk2(acc[m2][3],v0[3],v1[3]);
                #pragma unroll
                for (int r=0;r<2;r++){
                    int row = rh*16 + 2*m2 + r;
                    const float* vv = r ? v1 : v0;
                    #pragma unroll
                    for (int j=0;j<4;j++){
                        int c = c0 + j;
                        dst[row*512 + c] = tanhf(vv[j] + Bv[c]);
                    }
                }
            }
        }
    }
    gsync();

    // ---------- P2: attention scores on all 128 blocks ----------
    {
        __shared__ float sg[512], sa[512];
        const int b  = blk & 31;
        const int lq = blk >> 5;                  // 4 quarters of 25 l's
        for (int i = tid; i < 512; i += 256){
            sg[i] = g_gamma[b*512+i];
            sa[i] = g_alpha[b*512+i];
        }
        __syncthreads();
        for (int l0 = warp; l0 < 25; l0 += 8){
            int l = lq*25 + l0;
            const float* ph = g_phi_hs  + ((size_t)b*100 + l)*512;
            const float* pf = g_phi_fds + ((size_t)b*100 + l)*512;
            float s1=0.f, s2=0.f;
            #pragma unroll
            for (int k=lane; k<512; k+=32){ s1 += ph[k]*sg[k]; s2 += pf[k]*sa[k]; }
            #pragma unroll
            for (int o=16;o;o>>=1){ s1 += __shfl_xor_sync(~0u,s1,o); s2 += __shfl_xor_sync(~0u,s2,o); }
            if (lane==0){ g_sch[b*100+l]=s1; g_scf[b*100+l]=s2; }
        }
        __syncthreads();
    }
    gsync();

    // ---------- P3: softmaxes + context on all 128 blocks (4 h-slices/batch) ----
    {
        __shared__ float sh2[100], sf2[100], sw2[104], aux2[3];
        const int b  = blk >> 2;
        const int hq = blk & 3;
        for (int i = tid; i < 100; i += 256){
            sh2[i] = g_sch[b*100+i];
            sf2[i] = g_scf[b*100+i];
        }
        __syncthreads();
        if (warp < 2){
            float* s = warp ? sf2 : sh2;
            float mx = -1e30f;
            for (int l=lane;l<100;l+=32) mx = fmaxf(mx, s[l]);
            #pragma unroll
            for (int o=16;o;o>>=1) mx = fmaxf(mx, __shfl_xor_sync(~0u,mx,o));
            float sum = 0.f;
            for (int l=lane;l<100;l+=32){ float e = expf(s[l]-mx); s[l]=e; sum+=e; }
            #pragma unroll
            for (int o=16;o;o>>=1) sum += __shfl_xor_sync(~0u,sum,o);
            if (lane==0) aux2[warp] = EPSF + sum;
        }
        __syncthreads();
        if (warp == 0){
            float d1 = aux2[0], d2 = aux2[1];
            float wsum = 0.f;
            for (int l=lane;l<100;l+=32){ float w = (sh2[l]/d1)*(sf2[l]/d2); sw2[l]=w; wsum += w; }
            #pragma unroll
            for (int o=16;o;o>>=1) wsum += __shfl_xor_sync(~0u,wsum,o);
            if (lane==0) aux2[2] = EPSF + wsum;
        }
        __syncthreads();
        if (warp == 0){
            float d = aux2[2];
            for (int l=lane;l<100;l+=32) sw2[l] = sw2[l]/d;
            if (lane < 4) sw2[100+lane] = 0.f;
        }
        __syncthreads();
        if (tid < 128){
            int h = hq*128 + tid;
            const float4* e = (const float4*)(g_encT + ((size_t)b*512 + h)*104);
            float c2 = 0.f;
            #pragma unroll
            for (int l4=0; l4<26; l4++){
                float4 ev = e[l4];
                int l = l4*4;
                c2 += sw2[l+0]*ev.x + sw2[l+1]*ev.y + sw2[l+2]*ev.z + sw2[l+3]*ev.w;
            }
            g_ctx[b*512+h] = c2;
        }
        __syncthreads();
    }
    gsync();

    // ---------- P4: att = tanh([ctx|ot] @ Wo + bo), blocks 0..15 (32 cols) ------
    if (blk < 16){
        for (int idx = tid; idx < 32*1024; idx += 256){
            int m = idx >> 10, k = idx & 1023;
            float v = (k < 512) ? g_ctx[m*512+k] : g_ot[m*512+k-512];
            sm[k*36 + m] = v;
        }
        __syncthreads();
        const int colbase = blk * 32;
        u64 acc[8][4];
        if (gemm32<16,1024>(sm, Wo, colbase, acc)){
            const int cg = tid & 7, rh = (tid >> 3) & 1;
            const int c0 = colbase + cg*4;
            float* dst = g_att[t&1];
            #pragma unroll
            for (int m2=0;m2<8;m2++){
                float v0[4], v1[4];
                upk2(acc[m2][0],v0[0],v1[0]); upk2(acc[m2][1],v0[1],v1[1]);
                upk2(acc[m2][2],v0[2],v1[2]); upk2(acc[m2][3],v0[3],v1[3]);
                #pragma unroll
                for (int r=0;r<2;r++){
                    int row = rh*16 + 2*m2 + r;
                    bool fin = (t>0) && (t-1 >= lens[row]);
                    const float* vv = r ? v1 : v0;
                    #pragma unroll
                    for (int j=0;j<4;j++){
                        int c = c0 + j;
                        float v = tanhf(vv[j] + bo[c]);
                        dst[row*512 + c] = fin ? 0.f : v;
                    }
                }
            }
        }
    }
}

// ---- logits: grid 250 x 256, 128 cols/block, KS=4, 2 blocks/SM (R10-proven) ----
__global__ void __launch_bounds__(256)
logits_k(const float* __restrict__ oW, const float* __restrict__ ob,
         const int* __restrict__ lens, float* __restrict__ out, int t)
{
    extern __shared__ float sm[];
    const int tid = threadIdx.x, blk = blockIdx.x;
    const float* attb = g_att[t&1];

    for (int idx = tid; idx < 32*512; idx += 256){
        int m = idx >> 9, k = idx & 511;
        sm[k*36 + m] = attb[m*512 + k];
    }
    __syncthreads();

    const int cg = tid & 31;
    const int rh = (tid >> 5) & 1;
    const int ks = tid >> 6;

    u64 acc[8][4];
    #pragma unroll
    for (int i=0;i<8;i++){ acc[i][0]=0; acc[i][1]=0; acc[i][2]=0; acc[i][3]=0; }

    const float* wp = oW + (size_t)(ks*128)*32000 + blk*128 + cg*4;
    const float* ap = sm + (ks*128)*36 + rh*16;

    float4 wa[4], wb[4];
    load4v(wa, wp, 32000);
    #pragma unroll 1
    for (int j=0;j<15;j++){
        load4v(wb, wp, 32000);
        comp4v(acc, ap, wa);
        load4v(wa, wp, 32000);
        comp4v(acc, ap, wb);
    }
    load4v(wb, wp, 32000);
    comp4v(acc, ap, wa);
    comp4v(acc, ap, wb);

    __syncthreads();
    u64* red = (u64*)sm;
    u64* mr  = red + (size_t)tid*33;
    #pragma unroll
    for (int m2=0;m2<8;m2++){
        mr[4*m2+0]=acc[m2][0]; mr[4*m2+1]=acc[m2][1];
        mr[4*m2+2]=acc[m2][2]; mr[4*m2+3]=acc[m2][3];
    }
    __syncthreads();
    for (int s=2; s>=1; s>>=1){
        if (ks < s){
            const u64* pr = red + (size_t)(tid + s*64)*33;
            #pragma unroll
            for (int m2=0;m2<8;m2++){
                acc[m2][0]=fadd2(acc[m2][0],pr[4*m2+0]);
                acc[m2][1]=fadd2(acc[m2][1],pr[4*m2+1]);
                acc[m2][2]=fadd2(acc[m2][2],pr[4*m2+2]);
                acc[m2][3]=fadd2(acc[m2][3],pr[4*m2+3]);
            }
            if (s>1){
                #pragma unroll
                for (int m2=0;m2<8;m2++){
                    mr[4*m2+0]=acc[m2][0]; mr[4*m2+1]=acc[m2][1];
                    mr[4*m2+2]=acc[m2][2]; mr[4*m2+3]=acc[m2][3];
                }
            }
        }
        __syncthreads();
    }
    if (ks == 0){
        const int c0 = blk*128 + cg*4;
        #pragma unroll
        for (int m2=0;m2<8;m2++){
            float v0[4], v1[4];
            upk2(acc[m2][0],v0[0],v1[0]); upk2(acc[m2][1],v0[1],v1[1]);
            upk2(acc[m2][2],v0[2],v1[2]); upk2(acc[m2][3],v0[3],v1[3]);
            #pragma unroll
            for (int r=0;r<2;r++){
                int row = rh*16 + 2*m2 + r;
                bool fin = (t>0) && (t-1 >= lens[row]);
                const float* vv = r ? v1 : v0;
                float* op = out + (size_t)row*2080000 + (size_t)t*32000 + c0;
                #pragma unroll
                for (int j=0;j<4;j++)
                    op[j] = fin ? 0.f : (vv[j] + ob[c0+j]);
            }
        }
    }
}

// ---- final h/c ----
__global__ void fin_k(float* __restrict__ out)
{
    int i = blockIdx.x*256 + threadIdx.x;
    if (i < 16384){
        out[66560000 + i]         = g_hbuf[1][i];
        out[66560000 + 16384 + i] = g_cbuf[1][i];
    }
}

// ---------------- host ----------------
extern "C" void kernel_launch(void* const* d_in, const int* in_sizes, int n_in,
                              void* d_out, int out_size)
{
    const float* h0   = (const float*)d_in[0];
    const float* c0   = (const float*)d_in[1];
    const float* inp  = (const float*)d_in[2];
    const float* enc  = (const float*)d_in[3];
    const float* fld  = (const float*)d_in[4];
    const float* emb  = (const float*)d_in[5];
    const float* lW   = (const float*)d_in[6];
    const float* lb   = (const float*)d_in[7];
    const float* Wh   = (const float*)d_in[8];
    const float* bh   = (const float*)d_in[9];
    const float* Ws   = (const float*)d_in[10];
    const float* bs   = (const float*)d_in[11];
    const float* Wr   = (const float*)d_in[12];
    const float* br   = (const float*)d_in[13];
    const float* Wf   = (const float*)d_in[14];
    const float* bf   = (const float*)d_in[15];
    const float* Wo   = (const float*)d_in[16];
    const float* bo   = (const float*)d_in[17];
    const float* oW   = (const float*)d_in[18];
    const float* ob   = (const float*)d_in[19];
    const int*   lens = (const int*)  d_in[20];
    float* out = (float*)d_out;

    const int SM_PRE   = 512*36*4;      // 73728
    const int SM_CHAIN = 1024*36*4;     // 147456
    const int SM_LOG   = 512*36*4;      // 73728

    cudaFuncSetAttribute((const void*)pre_all,  cudaFuncAttributeMaxDynamicSharedMemorySize, SM_PRE);
    cudaFuncSetAttribute((const void*)chain_k,  cudaFuncAttributeMaxDynamicSharedMemorySize, SM_CHAIN);
    cudaFuncSetAttribute((const void*)logits_k, cudaFuncAttributeMaxDynamicSharedMemorySize, SM_LOG);

    cudaStream_t s2;
    cudaStreamCreateWithFlags(&s2, cudaStreamNonBlocking);
    cudaEvent_t eA, eB0, eB1;
    cudaEventCreateWithFlags(&eA,  cudaEventDisableTiming);
    cudaEventCreateWithFlags(&eB0, cudaEventDisableTiming);
    cudaEventCreateWithFlags(&eB1, cudaEventDisableTiming);

    pre_all<<<1000, 256, SM_PRE>>>(h0, c0, enc, fld, emb, inp, lW, lb,
                                   Wh, bh, Wf, bf);
    dummy_k<<<1, 32>>>();

    const float* lWh = lW + (size_t)512*2048;
    for (int t = 0; t < 65; t++){
        if (t > 0){
            cudaStreamWaitEvent(s2, eA, 0);                 // after chain(t-1)
            logits_k<<<250, 256, SM_LOG, s2>>>(oW, ob, lens, out, t-1);
            cudaEventRecord(((t-1)&1) ? eB1 : eB0, s2);
        }
        if (t >= 2) cudaStreamWaitEvent(0, (t&1) ? eB1 : eB0, 0);  // WAR on g_att[t&1]
        chain_k<<<128, 256, SM_CHAIN>>>(lWh, Ws, bs, Wr, br, Wo, bo, lens, t);
        cudaEventRecord(eA, 0);
    }
    cudaStreamWaitEvent(s2, eA, 0);
    logits_k<<<250, 256, SM_LOG, s2>>>(oW, ob, lens, out, 64);
    cudaEventRecord(eB0, s2);
    cudaStreamWaitEvent(0, eB0, 0);
    cudaStreamWaitEvent(0, eB1, 0);
    fin_k<<<64, 256>>>(out);

    (void)in_sizes; (void)n_in; (void)out_size;
}

// round 14
// speedup vs baseline: 1.2840x; 1.0627x over previous
#include <cuda_runtime.h>
#include <math.h>

#define SOSID 2
#define EPSF  1e-6f

typedef unsigned long long u64;

// ---------------- persistent device state ----------------
__device__ float g_phi_hs[3200*512];
__device__ float g_phi_fds[3200*512];
__device__ float g_zx[2080*2048];
__device__ float g_encT[32*512*104];
__device__ float g_hbuf[2][32*512];
__device__ float g_cbuf[2][32*512];
__device__ float g_ot[32*512];
__device__ float g_gamma[32*512];
__device__ float g_alpha[32*512];
__device__ float g_ctx[32*512];
__device__ float g_att_all[2080*512];  // att for ALL steps; logits chunks consume later
__device__ float g_sch[3200];
__device__ float g_scf[3200];
__device__ int          g_cnt;
__device__ volatile int g_gen;

// ---------------- helpers ----------------
__device__ __forceinline__ u64 pk2(float lo, float hi){
    u64 r; asm("mov.b64 %0, {%1,%2};" : "=l"(r) : "f"(lo), "f"(hi)); return r;
}
__device__ __forceinline__ void upk2(u64 v, float& lo, float& hi){
    asm("mov.b64 {%0,%1}, %2;" : "=f"(lo), "=f"(hi) : "l"(v));
}
__device__ __forceinline__ u64 ffma2(u64 a, u64 b, u64 c){
    u64 r; asm("fma.rn.f32x2 %0, %1, %2, %3;" : "=l"(r) : "l"(a), "l"(b), "l"(c)); return r;
}
__device__ __forceinline__ u64 fadd2(u64 a, u64 b){
    u64 r; asm("add.rn.f32x2 %0, %1, %2;" : "=l"(r) : "l"(a), "l"(b)); return r;
}
__device__ __forceinline__ float sigf(float x){ return 1.f/(1.f+expf(-x)); }

// global barrier for the fused chain kernel (gridDim.x blocks)
__device__ __forceinline__ void gsync(){
    __threadfence();
    __syncthreads();
    if (threadIdx.x == 0){
        int g = g_gen;
        if (atomicAdd(&g_cnt, 1) == (int)gridDim.x - 1){
            g_cnt = 0;
            __threadfence();
            g_gen = g + 1;
        } else {
            while (g_gen == g) { __nanosleep(20); }
        }
    }
    __syncthreads();
}

// ---------------- pipelined inner-loop building blocks ----------------
__device__ __forceinline__ void load4v(float4 (&w)[4], const float*& wp, int ldw){
    #pragma unroll
    for (int i=0;i<4;i++){ w[i] = *(const float4*)wp; wp += ldw; }
}
__device__ __forceinline__ void comp4v(u64 (&acc)[8][4], const float*& ap, const float4 (&w)[4]){
    #pragma unroll
    for (int i=0;i<4;i++){
        u64 b0=pk2(w[i].x,w[i].x), b1=pk2(w[i].y,w[i].y),
            b2=pk2(w[i].z,w[i].z), b3=pk2(w[i].w,w[i].w);
        u64 aa[8];
        #pragma unroll
        for (int m=0;m<8;m++) aa[m]=((const u64*)ap)[m];
        ap += 36;
        #pragma unroll
        for (int m=0;m<8;m++){
            acc[m][0]=ffma2(aa[m],b0,acc[m][0]);
            acc[m][1]=ffma2(aa[m],b1,acc[m][1]);
            acc[m][2]=ffma2(aa[m],b2,acc[m][2]);
            acc[m][3]=ffma2(aa[m],b3,acc[m][3]);
        }
    }
}
__device__ __forceinline__ void load4g(float (&w)[16], const float*& wp){
    #pragma unroll
    for (int i=0;i<4;i++){
        w[i*4+0]=wp[0]; w[i*4+1]=wp[512]; w[i*4+2]=wp[1024]; w[i*4+3]=wp[1536];
        wp += 2048;
    }
}
__device__ __forceinline__ void comp4gb(u64 (&acc)[4][4], const float*& ap, const float (&w)[16]){
    #pragma unroll
    for (int i=0;i<4;i++){
        u64 b0=pk2(w[i*4+0],w[i*4+0]), b1=pk2(w[i*4+1],w[i*4+1]),
            b2=pk2(w[i*4+2],w[i*4+2]), b3=pk2(w[i*4+3],w[i*4+3]);
        u64 a0=((const u64*)ap)[0], a1=((const u64*)ap)[1],
            a2=((const u64*)ap)[2], a3=((const u64*)ap)[3];
        ap += 36;
        acc[0][0]=ffma2(a0,b0,acc[0][0]); acc[1][0]=ffma2(a1,b0,acc[1][0]);
        acc[2][0]=ffma2(a2,b0,acc[2][0]); acc[3][0]=ffma2(a3,b0,acc[3][0]);
        acc[0][1]=ffma2(a0,b1,acc[0][1]); acc[1][1]=ffma2(a1,b1,acc[1][1]);
        acc[2][1]=ffma2(a2,b1,acc[2][1]); acc[3][1]=ffma2(a3,b1,acc[3][1]);
        acc[0][2]=ffma2(a0,b2,acc[0][2]); acc[1][2]=ffma2(a1,b2,acc[1][2]);
        acc[2][2]=ffma2(a2,b2,acc[2][2]); acc[3][2]=ffma2(a3,b2,acc[3][2]);
        acc[0][3]=ffma2(a0,b3,acc[0][3]); acc[1][3]=ffma2(a1,b3,acc[1][3]);
        acc[2][3]=ffma2(a2,b3,acc[2][3]); acc[3][3]=ffma2(a3,b3,acc[3][3]);
    }
}

// small-N f32x2 GEMM phase: 32 cols/block, tree-reduced K split (16-way)
template<int KSPLIT, int KTOT>
__device__ __forceinline__ bool gemm32(float* sm, const float* __restrict__ W,
                                       int colbase, u64 (&acc)[8][4])
{
    const int tid = threadIdx.x;
    const int cg = tid & 7;
    const int rh = (tid >> 3) & 1;
    const int ks = tid >> 4;
    constexpr int KPER = KTOT / KSPLIT;
    constexpr int NT2  = (KPER/4)/2;

    #pragma unroll
    for (int i=0;i<8;i++){ acc[i][0]=0; acc[i][1]=0; acc[i][2]=0; acc[i][3]=0; }

    const float* wp = W + (size_t)(ks*KPER)*512 + colbase + cg*4;
    const float* ap = sm + (ks*KPER)*36 + rh*16;

    float4 wa[4], wb[4];
    load4v(wa, wp, 512);
    #pragma unroll 1
    for (int j=0;j<NT2-1;j++){
        load4v(wb, wp, 512);
        comp4v(acc, ap, wa);
        load4v(wa, wp, 512);
        comp4v(acc, ap, wb);
    }
    load4v(wb, wp, 512);
    comp4v(acc, ap, wa);
    comp4v(acc, ap, wb);

    __syncthreads();
    u64* red = (u64*)sm;
    u64* mr  = red + (size_t)tid*33;
    #pragma unroll
    for (int m2=0;m2<8;m2++){
        mr[4*m2+0]=acc[m2][0]; mr[4*m2+1]=acc[m2][1];
        mr[4*m2+2]=acc[m2][2]; mr[4*m2+3]=acc[m2][3];
    }
    __syncthreads();
    for (int s=KSPLIT/2; s>=1; s>>=1){
        if (ks < s){
            const u64* pr = red + (size_t)(tid + s*16)*33;
            #pragma unroll
            for (int m2=0;m2<8;m2++){
                acc[m2][0]=fadd2(acc[m2][0],pr[4*m2+0]);
                acc[m2][1]=fadd2(acc[m2][1],pr[4*m2+1]);
                acc[m2][2]=fadd2(acc[m2][2],pr[4*m2+2]);
                acc[m2][3]=fadd2(acc[m2][3],pr[4*m2+3]);
            }
            if (s>1){
                #pragma unroll
                for (int m2=0;m2<8;m2++){
                    mr[4*m2+0]=acc[m2][0]; mr[4*m2+1]=acc[m2][1];
                    mr[4*m2+2]=acc[m2][2]; mr[4*m2+3]=acc[m2][3];
                }
            }
        }
        __syncthreads();
    }
    return ks == 0;
}

// ================= precompute GEMM (device fn) ====
template<int K, int AMODE, int EPI>
__device__ void dev_g32(float* sm,
    const float* __restrict__ W, const float* __restrict__ Bv,
    const float* __restrict__ A, int lda, int ldw,
    const float* __restrict__ p1, int rowBase, int tt, int colblk)
{
    const int tid = threadIdx.x;
    const int cg  = tid & 63;
    const int rh  = (tid >> 6) & 1;
    const int ks  = tid >> 7;

    for (int idx = tid; idx < 32*K; idx += 256){
        int m = idx / K, k = idx - m*K;
        float v;
        if (AMODE==0) v = A[(size_t)(rowBase+m)*lda + k];
        else          v = (tt==0) ? A[SOSID*512 + k]
                                  : p1[((size_t)m*64 + (tt-1))*512 + k];
        sm[k*36 + m] = v;
    }
    __syncthreads();

    u64 acc[8][4];
    #pragma unroll
    for (int i=0;i<8;i++){ acc[i][0]=0; acc[i][1]=0; acc[i][2]=0; acc[i][3]=0; }

    const float* wp = W + (size_t)(ks*(K/2))*ldw + colblk*256 + cg*4;
    const float* ap = sm + (ks*(K/2))*36 + rh*16;
    const int NT2 = ((K/2)/4)/2;

    float4 wa[4], wb[4];
    load4v(wa, wp, ldw);
    #pragma unroll 1
    for (int j=0;j<NT2-1;j++){
        load4v(wb, wp, ldw);
        comp4v(acc, ap, wa);
        load4v(wa, wp, ldw);
        comp4v(acc, ap, wb);
    }
    load4v(wb, wp, ldw);
    comp4v(acc, ap, wa);
    comp4v(acc, ap, wb);

    __syncthreads();
    u64* red = (u64*)sm;
    u64* mr  = red + (size_t)tid*33;
    #pragma unroll
    for (int m2=0;m2<8;m2++){
        mr[4*m2+0]=acc[m2][0]; mr[4*m2+1]=acc[m2][1];
        mr[4*m2+2]=acc[m2][2]; mr[4*m2+3]=acc[m2][3];
    }
    __syncthreads();
    if (ks == 0){
        const u64* pr = red + (size_t)(tid + 128)*33;
        #pragma unroll
        for (int m2=0;m2<8;m2++){
            acc[m2][0]=fadd2(acc[m2][0],pr[4*m2+0]);
            acc[m2][1]=fadd2(acc[m2][1],pr[4*m2+1]);
            acc[m2][2]=fadd2(acc[m2][2],pr[4*m2+2]);
            acc[m2][3]=fadd2(acc[m2][3],pr[4*m2+3]);
        }
        int c0 = colblk*256 + cg*4;
        #pragma unroll
        for (int m2=0;m2<8;m2++){
            float v0[4], v1[4];
            upk2(acc[m2][0],v0[0],v1[0]); upk2(acc[m2][1],v0[1],v1[1]);
            upk2(acc[m2][2],v0[2],v1[2]); upk2(acc[m2][3],v0[3],v1[3]);
            #pragma unroll
            for (int r=0;r<2;r++){
                int row = rowBase + rh*16 + 2*m2 + r;
                const float* vv = r ? v1 : v0;
                #pragma unroll
                for (int j=0;j<4;j++){
                    int c = c0 + j;
                    float x = vv[j] + Bv[c];
                    if (EPI==0)      g_phi_hs [(size_t)row*512 +c] = tanhf(x);
                    else if (EPI==1) g_phi_fds[(size_t)row*512 +c] = tanhf(x);
                    else             g_zx     [(size_t)row*2048+c] = x;
                }
            }
        }
    }
    __syncthreads();
}

// ---- pre_all: h/c init + encT + all precompute GEMMs ----
__global__ void __launch_bounds__(256)
pre_all(const float* __restrict__ h0,  const float* __restrict__ c0,
        const float* __restrict__ enc, const float* __restrict__ fld,
        const float* __restrict__ emb, const float* __restrict__ inp,
        const float* __restrict__ lW,  const float* __restrict__ lb,
        const float* __restrict__ Wh,  const float* __restrict__ bh,
        const float* __restrict__ Wf,  const float* __restrict__ bf)
{
    extern __shared__ float sm[];
    const int task = blockIdx.x;
    const int tid  = threadIdx.x;

    if (task < 200){
        dev_g32<512,0,0>(sm, Wh, bh, enc, 512, 512, nullptr, (task>>1)*32, 0, task&1);
    } else if (task < 400){
        int x = task - 200;
        dev_g32<64,0,1>(sm, Wf, bf, fld, 64, 512, nullptr, (x>>1)*32, 0, x&1);
    } else if (task < 920){
        int x = task - 400;
        dev_g32<512,1,2>(sm, lW, lb, emb, 512, 2048, inp, (x>>3)*32, x>>3, x&7);
    } else {
        const int gt = (task-920)*256 + tid, gs = 80*256;
        for (int i=gt; i<16384; i+=gs){ g_hbuf[0][i]=h0[i]; g_cbuf[0][i]=c0[i]; }
        for (int i=gt; i<32*512*104; i+=gs){
            int l=i%104; int hh=(i/104)&511; int b=i/(104*512);
            g_encT[i] = (l<100) ? enc[((size_t)b*100+l)*512+hh] : 0.f;
        }
    }
}

// ================= fused chain kernel (R12-proven, writes g_att_all[t]) ========
__global__ void __launch_bounds__(256, 1)
chain_k(const float* __restrict__ lWh,
        const float* __restrict__ Ws, const float* __restrict__ bs,
        const float* __restrict__ Wr, const float* __restrict__ br,
        const float* __restrict__ Wo, const float* __restrict__ bo,
        const int* __restrict__ lens, int t)
{
    extern __shared__ float sm[];
    const int blk = blockIdx.x;
    const int tid = threadIdx.x;
    const int warp = tid >> 5, lane = tid & 31;

    // ---------- P0: LSTM on blocks 0..63 ----------
    if (blk < 64){
        const int pb = t & 1, cb = pb ^ 1;
        const int hbase = blk * 8;

        for (int idx = tid; idx < 32*512; idx += 256){
            int m = idx >> 9, k = idx & 511;
            sm[k*36 + m] = g_hbuf[pb][m*512 + k];
        }
        __syncthreads();

        const int cg = tid & 7;
        const int rg = (tid >> 3) & 3;
        const int ks = tid >> 5;

        u64 acc[4][4];
        #pragma unroll
        for (int i=0;i<4;i++){ acc[i][0]=0; acc[i][1]=0; acc[i][2]=0; acc[i][3]=0; }

        const float* wp = lWh + (size_t)(ks*64)*2048 + hbase + cg;
        const float* ap = sm + (ks*64)*36 + rg*8;

        float wa[16], wb[16];
        load4g(wa, wp);
        #pragma unroll 1
        for (int j=0;j<7;j++){
            load4g(wb, wp);
            comp4gb(acc, ap, wa);
            load4g(wa, wp);
            comp4gb(acc, ap, wb);
        }
        load4g(wb, wp);
        comp4gb(acc, ap, wa);
        comp4gb(acc, ap, wb);

        __syncthreads();
        u64* red = (u64*)sm;
        u64* mr  = red + (size_t)tid*16;
        #pragma unroll
        for (int p=0;p<4;p++){
            mr[4*p+0]=acc[p][0]; mr[4*p+1]=acc[p][1];
            mr[4*p+2]=acc[p][2]; mr[4*p+3]=acc[p][3];
        }
        __syncthreads();
        for (int s=4; s>=1; s>>=1){
            if (ks < s){
                const u64* pr = red + (size_t)(tid + s*32)*16;
                #pragma unroll
                for (int p=0;p<4;p++){
                    acc[p][0]=fadd2(acc[p][0],pr[4*p+0]);
                    acc[p][1]=fadd2(acc[p][1],pr[4*p+1]);
                    acc[p][2]=fadd2(acc[p][2],pr[4*p+2]);
                    acc[p][3]=fadd2(acc[p][3],pr[4*p+3]);
                }
                if (s>1){
                    #pragma unroll
                    for (int p=0;p<4;p++){
                        mr[4*p+0]=acc[p][0]; mr[4*p+1]=acc[p][1];
                        mr[4*p+2]=acc[p][2]; mr[4*p+3]=acc[p][3];
                    }
                }
            }
            __syncthreads();
        }

        if (ks == 0){
            const int h = hbase + cg;
            #pragma unroll
            for (int p=0;p<4;p++){
                float zi[2],zj[2],zf[2],zo[2];
                upk2(acc[p][0],zi[0],zi[1]); upk2(acc[p][1],zj[0],zj[1]);
                upk2(acc[p][2],zf[0],zf[1]); upk2(acc[p][3],zo[0],zo[1]);
                #pragma unroll
                for (int r=0;r<2;r++){
                    int b = rg*8 + 2*p + r;
                    const float* zxp = g_zx + ((size_t)(t*32+b))*2048 + h;
                    float vi = zi[r] + zxp[0];
                    float vj = zj[r] + zxp[512];
                    float vf = zf[r] + zxp[1024];
                    float vo = zo[r] + zxp[1536];
                    float cp = g_cbuf[pb][b*512+h];
                    float hp = g_hbuf[pb][b*512+h];
                    float cn = sigf(vf+1.f)*cp + sigf(vi)*tanhf(vj);
                    float hn = sigf(vo)*tanhf(cn);
                    bool fin = (t>0) && (t-1 >= lens[b]);
                    g_ot[b*512+h]       = fin ? 0.f : hn;
                    g_hbuf[cb][b*512+h] = fin ? hp  : hn;
                    g_cbuf[cb][b*512+h] = fin ? cp  : cn;
                }
            }
        }
    }
    gsync();

    // ---------- P1: gamma/alpha on blocks 0..31 ----------
    if (blk < 32){
        for (int idx = tid; idx < 32*512; idx += 256){
            int m = idx >> 9, k = idx & 511;
            sm[k*36 + m] = g_ot[m*512 + k];
        }
        __syncthreads();
        const float* W  = (blk < 16) ? Ws : Wr;
        const float* Bv = (blk < 16) ? bs : br;
        const int colbase = (blk & 15) * 32;
        u64 acc[8][4];
        if (gemm32<16,512>(sm, W, colbase, acc)){
            const int cg = tid & 7, rh = (tid >> 3) & 1;
            const int c0 = colbase + cg*4;
            float* dst = (blk < 16) ? g_gamma : g_alpha;
            #pragma unroll
            for (int m2=0;m2<8;m2++){
                float v0[4], v1[4];
                upk2(acc[m2][0],v0[0],v1[0]); upk2(acc[m2][1],v0[1],v1[1]);
                upk2(acc[m2][2],v0[2],v1[2]); upk2(acc[m2][3],v0[3],v1[3]);
                #pragma unroll
                for (int r=0;r<2;r++){
                    int row = rh*16 + 2*m2 + r;
                    const float* vv = r ? v1 : v0;
                    #pragma unroll
                    for (int j=0;j<4;j++){
                        int c = c0 + j;
                        dst[row*512 + c] = tanhf(vv[j] + Bv[c]);
                    }
                }
            }
        }
    }
    gsync();

    // ---------- P2: attention scores on all 128 blocks ----------
    {
        __shared__ float sg[512], sa[512];
        const int b  = blk & 31;
        const int lq = blk >> 5;
        for (int i = tid; i < 512; i += 256){
            sg[i] = g_gamma[b*512+i];
            sa[i] = g_alpha[b*512+i];
        }
        __syncthreads();
        for (int l0 = warp; l0 < 25; l0 += 8){
            int l = lq*25 + l0;
            const float* ph = g_phi_hs  + ((size_t)b*100 + l)*512;
            const float* pf = g_phi_fds + ((size_t)b*100 + l)*512;
            float s1=0.f, s2=0.f;
            #pragma unroll
            for (int k=lane; k<512; k+=32){ s1 += ph[k]*sg[k]; s2 += pf[k]*sa[k]; }
            #pragma unroll
            for (int o=16;o;o>>=1){ s1 += __shfl_xor_sync(~0u,s1,o); s2 += __shfl_xor_sync(~0u,s2,o); }
            if (lane==0){ g_sch[b*100+l]=s1; g_scf[b*100+l]=s2; }
        }
        __syncthreads();
    }
    gsync();

    // ---------- P3: softmaxes + context on all 128 blocks ----------
    {
        __shared__ float sh2[100], sf2[100], sw2[104], aux2[3];
        const int b  = blk >> 2;
        const int hq = blk & 3;
        for (int i = tid; i < 100; i += 256){
            sh2[i] = g_sch[b*100+i];
            sf2[i] = g_scf[b*100+i];
        }
        __syncthreads();
        if (warp < 2){
            float* s = warp ? sf2 : sh2;
            float mx = -1e30f;
            for (int l=lane;l<100;l+=32) mx = fmaxf(mx, s[l]);
            #pragma unroll
            for (int o=16;o;o>>=1) mx = fmaxf(mx, __shfl_xor_sync(~0u,mx,o));
            float sum = 0.f;
            for (int l=lane;l<100;l+=32){ float e = expf(s[l]-mx); s[l]=e; sum+=e; }
            #pragma unroll
            for (int o=16;o;o>>=1) sum += __shfl_xor_sync(~0u,sum,o);
            if (lane==0) aux2[warp] = EPSF + sum;
        }
        __syncthreads();
        if (warp == 0){
            float d1 = aux2[0], d2 = aux2[1];
            float wsum = 0.f;
            for (int l=lane;l<100;l+=32){ float w = (sh2[l]/d1)*(sf2[l]/d2); sw2[l]=w; wsum += w; }
            #pragma unroll
            for (int o=16;o;o>>=1) wsum += __shfl_xor_sync(~0u,wsum,o);
            if (lane==0) aux2[2] = EPSF + wsum;
        }
        __syncthreads();
        if (warp == 0){
            float d = aux2[2];
            for (int l=lane;l<100;l+=32) sw2[l] = sw2[l]/d;
            if (lane < 4) sw2[100+lane] = 0.f;
        }
        __syncthreads();
        if (tid < 128){
            int h = hq*128 + tid;
            const float4* e = (const float4*)(g_encT + ((size_t)b*512 + h)*104);
            float c2 = 0.f;
            #pragma unroll
            for (int l4=0; l4<26; l4++){
                float4 ev = e[l4];
                int l = l4*4;
                c2 += sw2[l+0]*ev.x + sw2[l+1]*ev.y + sw2[l+2]*ev.z + sw2[l+3]*ev.w;
            }
            g_ctx[b*512+h] = c2;
        }
        __syncthreads();
    }
    gsync();

    // ---------- P4: att(t) = tanh([ctx|ot] @ Wo + bo), blocks 0..15 ------------
    if (blk < 16){
        for (int idx = tid; idx < 32*1024; idx += 256){
            int m = idx >> 10, k = idx & 1023;
            float v = (k < 512) ? g_ctx[m*512+k] : g_ot[m*512+k-512];
            sm[k*36 + m] = v;
        }
        __syncthreads();
        const int colbase = blk * 32;
        u64 acc[8][4];
        if (gemm32<16,1024>(sm, Wo, colbase, acc)){
            const int cg = tid & 7, rh = (tid >> 3) & 1;
            const int c0 = colbase + cg*4;
            float* dst = g_att_all + (size_t)t*16384;
            #pragma unroll
            for (int m2=0;m2<8;m2++){
                float v0[4], v1[4];
                upk2(acc[m2][0],v0[0],v1[0]); upk2(acc[m2][1],v0[1],v1[1]);
                upk2(acc[m2][2],v0[2],v1[2]); upk2(acc[m2][3],v0[3],v1[3]);
                #pragma unroll
                for (int r=0;r<2;r++){
                    int row = rh*16 + 2*m2 + r;
                    bool fin = (t>0) && (t-1 >= lens[row]);
                    const float* vv = r ? v1 : v0;
                    #pragma unroll
                    for (int j=0;j<4;j++){
                        int c = c0 + j;
                        float v = tanhf(vv[j] + bo[c]);
                        dst[row*512 + c] = fin ? 0.f : v;
                    }
                }
            }
        }
    }
}

// ---- logits chunk: grid 250 x 256; each block does its 128 cols for nt steps --
__global__ void __launch_bounds__(256)
logits_chunk(const float* __restrict__ oW, const float* __restrict__ ob,
             const int* __restrict__ lens, float* __restrict__ out, int t0, int nt)
{
    extern __shared__ float sm[];
    const int tid = threadIdx.x, blk = blockIdx.x;
    const int cg = tid & 31;
    const int rh = (tid >> 5) & 1;
    const int ks = tid >> 6;

    for (int tt = t0; tt < t0 + nt; tt++){
        const float* attb = g_att_all + (size_t)tt*16384;
        __syncthreads();
        for (int idx = tid; idx < 32*512; idx += 256){
            int m = idx >> 9, k = idx & 511;
            sm[k*36 + m] = attb[m*512 + k];
        }
        __syncthreads();

        u64 acc[8][4];
        #pragma unroll
        for (int i=0;i<8;i++){ acc[i][0]=0; acc[i][1]=0; acc[i][2]=0; acc[i][3]=0; }

        const float* wp = oW + (size_t)(ks*128)*32000 + blk*128 + cg*4;
        const float* ap = sm + (ks*128)*36 + rh*16;

        float4 wa[4], wb[4];
        load4v(wa, wp, 32000);
        #pragma unroll 1
        for (int j=0;j<15;j++){
            load4v(wb, wp, 32000);
            comp4v(acc, ap, wa);
            load4v(wa, wp, 32000);
            comp4v(acc, ap, wb);
        }
        load4v(wb, wp, 32000);
        comp4v(acc, ap, wa);
        comp4v(acc, ap, wb);

        __syncthreads();
        u64* red = (u64*)sm;
        u64* mr  = red + (size_t)tid*33;
        #pragma unroll
        for (int m2=0;m2<8;m2++){
            mr[4*m2+0]=acc[m2][0]; mr[4*m2+1]=acc[m2][1];
            mr[4*m2+2]=acc[m2][2]; mr[4*m2+3]=acc[m2][3];
        }
        __syncthreads();
        for (int s=2; s>=1; s>>=1){
            if (ks < s){
                const u64* pr = red + (size_t)(tid + s*64)*33;
                #pragma unroll
                for (int m2=0;m2<8;m2++){
                    acc[m2][0]=fadd2(acc[m2][0],pr[4*m2+0]);
                    acc[m2][1]=fadd2(acc[m2][1],pr[4*m2+1]);
                    acc[m2][2]=fadd2(acc[m2][2],pr[4*m2+2]);
                    acc[m2][3]=fadd2(acc[m2][3],pr[4*m2+3]);
                }
                if (s>1){
                    #pragma unroll
                    for (int m2=0;m2<8;m2++){
                        mr[4*m2+0]=acc[m2][0]; mr[4*m2+1]=acc[m2][1];
                        mr[4*m2+2]=acc[m2][2]; mr[4*m2+3]=acc[m2][3];
                    }
                }
            }
            __syncthreads();
        }
        if (ks == 0){
            const int c0 = blk*128 + cg*4;
            #pragma unroll
            for (int m2=0;m2<8;m2++){
                float v0[4], v1[4];
                upk2(acc[m2][0],v0[0],v1[0]); upk2(acc[m2][1],v0[1],v1[1]);
                upk2(acc[m2][2],v0[2],v1[2]); upk2(acc[m2][3],v0[3],v1[3]);
                #pragma unroll
                for (int r=0;r<2;r++){
                    int row = rh*16 + 2*m2 + r;
                    bool fin = (tt>0) && (tt-1 >= lens[row]);
                    const float* vv = r ? v1 : v0;
                    float* op = out + (size_t)row*2080000 + (size_t)tt*32000 + c0;
                    #pragma unroll
                    for (int j=0;j<4;j++)
                        op[j] = fin ? 0.f : (vv[j] + ob[c0+j]);
                }
            }
        }
    }
}

// ---- final h/c ----
__global__ void fin_k(float* __restrict__ out)
{
    int i = blockIdx.x*256 + threadIdx.x;
    if (i < 16384){
        out[66560000 + i]         = g_hbuf[1][i];
        out[66560000 + 16384 + i] = g_cbuf[1][i];
    }
}

// ---------------- host ----------------
extern "C" void kernel_launch(void* const* d_in, const int* in_sizes, int n_in,
                              void* d_out, int out_size)
{
    const float* h0   = (const float*)d_in[0];
    const float* c0   = (const float*)d_in[1];
    const float* inp  = (const float*)d_in[2];
    const float* enc  = (const float*)d_in[3];
    const float* fld  = (const float*)d_in[4];
    const float* emb  = (const float*)d_in[5];
    const float* lW   = (const float*)d_in[6];
    const float* lb   = (const float*)d_in[7];
    const float* Wh   = (const float*)d_in[8];
    const float* bh   = (const float*)d_in[9];
    const float* Ws   = (const float*)d_in[10];
    const float* bs   = (const float*)d_in[11];
    const float* Wr   = (const float*)d_in[12];
    const float* br   = (const float*)d_in[13];
    const float* Wf   = (const float*)d_in[14];
    const float* bf   = (const float*)d_in[15];
    const float* Wo   = (const float*)d_in[16];
    const float* bo   = (const float*)d_in[17];
    const float* oW   = (const float*)d_in[18];
    const float* ob   = (const float*)d_in[19];
    const int*   lens = (const int*)  d_in[20];
    float* out = (float*)d_out;

    const int SM_PRE   = 512*36*4;      // 73728
    const int SM_CHAIN = 1024*36*4;     // 147456
    const int SM_LOG   = 512*36*4;      // 73728

    cudaFuncSetAttribute((const void*)pre_all,      cudaFuncAttributeMaxDynamicSharedMemorySize, SM_PRE);
    cudaFuncSetAttribute((const void*)chain_k,      cudaFuncAttributeMaxDynamicSharedMemorySize, SM_CHAIN);
    cudaFuncSetAttribute((const void*)logits_chunk, cudaFuncAttributeMaxDynamicSharedMemorySize, SM_LOG);

    cudaStream_t s2;
    cudaStreamCreateWithFlags(&s2, cudaStreamNonBlocking);
    cudaEvent_t eC[5], eJ;
    for (int i=0;i<5;i++) cudaEventCreateWithFlags(&eC[i], cudaEventDisableTiming);
    cudaEventCreateWithFlags(&eJ, cudaEventDisableTiming);

    pre_all<<<1000, 256, SM_PRE>>>(h0, c0, enc, fld, emb, inp, lW, lb,
                                   Wh, bh, Wf, bf);

    const float* lWh = lW + (size_t)512*2048;
    const int chunk_end[5] = {15, 31, 47, 63, 64};
    const int chunk_t0[5]  = {0, 16, 32, 48, 64};
    const int chunk_nt[5]  = {16, 16, 16, 16, 1};
    int ci = 0;

    for (int t = 0; t < 65; t++){
        chain_k<<<128, 256, SM_CHAIN>>>(lWh, Ws, bs, Wr, br, Wo, bo, lens, t);
        if (ci < 5 && t == chunk_end[ci]){
            cudaEventRecord(eC[ci], 0);
            cudaStreamWaitEvent(s2, eC[ci], 0);
            logits_chunk<<<250, 256, SM_LOG, s2>>>(oW, ob, lens, out,
                                                   chunk_t0[ci], chunk_nt[ci]);
            ci++;
        }
    }
    cudaEventRecord(eJ, s2);
    cudaStreamWaitEvent(0, eJ, 0);
    fin_k<<<64, 256>>>(out);

    (void)in_sizes; (void)n_in; (void)out_size;
}

// round 15
// speedup vs baseline: 1.6142x; 1.2572x over previous
#include <cuda_runtime.h>
#include <math.h>

#define SOSID 2
#define EPSF  1e-6f

typedef unsigned long long u64;

// ---------------- persistent device state ----------------
__device__ float g_phi_hs[3200*512];
__device__ float g_phi_fds[3200*512];
__device__ float g_zx[2080*2048];
__device__ float g_encT[32*512*104];
__device__ float g_hbuf[2][32*512];
__device__ float g_cbuf[2][32*512];
__device__ float g_ot[32*512];
__device__ float g_gamma[32*512];
__device__ float g_alpha[32*512];
__device__ float g_ctx[32*512];
__device__ float g_att_all[2080*512];  // att for ALL steps
__device__ float g_sch[3200];
__device__ float g_scf[3200];
__device__ float g_zp[8*4*16384];      // LSTM partials: [ks][gate][b*512+h]
__device__ int          g_cnt;
__device__ volatile int g_gen;

// ---------------- helpers ----------------
__device__ __forceinline__ u64 pk2(float lo, float hi){
    u64 r; asm("mov.b64 %0, {%1,%2};" : "=l"(r) : "f"(lo), "f"(hi)); return r;
}
__device__ __forceinline__ void upk2(u64 v, float& lo, float& hi){
    asm("mov.b64 {%0,%1}, %2;" : "=f"(lo), "=f"(hi) : "l"(v));
}
__device__ __forceinline__ u64 ffma2(u64 a, u64 b, u64 c){
    u64 r; asm("fma.rn.f32x2 %0, %1, %2, %3;" : "=l"(r) : "l"(a), "l"(b), "l"(c)); return r;
}
__device__ __forceinline__ u64 fadd2(u64 a, u64 b){
    u64 r; asm("add.rn.f32x2 %0, %1, %2;" : "=l"(r) : "l"(a), "l"(b)); return r;
}
__device__ __forceinline__ float sigf(float x){ return 1.f/(1.f+expf(-x)); }

// global barrier (gridDim.x co-resident blocks)
__device__ __forceinline__ void gsync(){
    __threadfence();
    __syncthreads();
    if (threadIdx.x == 0){
        int g = g_gen;
        if (atomicAdd(&g_cnt, 1) == (int)gridDim.x - 1){
            g_cnt = 0;
            __threadfence();
            g_gen = g + 1;
        } else {
            while (g_gen == g) { __nanosleep(20); }
        }
    }
    __syncthreads();
}

// ---------------- inner-loop building blocks ----------------
__device__ __forceinline__ void load4v(float4 (&w)[4], const float*& wp, int ldw){
    #pragma unroll
    for (int i=0;i<4;i++){ w[i] = *(const float4*)wp; wp += ldw; }
}
// 8 row-pairs x 4 cols (precompute / logits)
__device__ __forceinline__ void comp4v(u64 (&acc)[8][4], const float*& ap, const float4 (&w)[4]){
    #pragma unroll
    for (int i=0;i<4;i++){
        u64 b0=pk2(w[i].x,w[i].x), b1=pk2(w[i].y,w[i].y),
            b2=pk2(w[i].z,w[i].z), b3=pk2(w[i].w,w[i].w);
        u64 aa[8];
        #pragma unroll
        for (int m=0;m<8;m++) aa[m]=((const u64*)ap)[m];
        ap += 36;
        #pragma unroll
        for (int m=0;m<8;m++){
            acc[m][0]=ffma2(aa[m],b0,acc[m][0]);
            acc[m][1]=ffma2(aa[m],b1,acc[m][1]);
            acc[m][2]=ffma2(aa[m],b2,acc[m][2]);
            acc[m][3]=ffma2(aa[m],b3,acc[m][3]);
        }
    }
}
// 4 row-pairs x 4 cols (P1/P4 phases)
__device__ __forceinline__ void comp4v4(u64 (&acc)[4][4], const float*& ap, const float4 (&w)[4]){
    #pragma unroll
    for (int i=0;i<4;i++){
        u64 b0=pk2(w[i].x,w[i].x), b1=pk2(w[i].y,w[i].y),
            b2=pk2(w[i].z,w[i].z), b3=pk2(w[i].w,w[i].w);
        u64 aa[4];
        #pragma unroll
        for (int m=0;m<4;m++) aa[m]=((const u64*)ap)[m];
        ap += 36;
        #pragma unroll
        for (int m=0;m<4;m++){
            acc[m][0]=ffma2(aa[m],b0,acc[m][0]);
            acc[m][1]=ffma2(aa[m],b1,acc[m][1]);
            acc[m][2]=ffma2(aa[m],b2,acc[m][2]);
            acc[m][3]=ffma2(aa[m],b3,acc[m][3]);
        }
    }
}
// gated loads (4 LSTM gate columns at stride 512)
__device__ __forceinline__ void load4g(float (&w)[16], const float*& wp){
    #pragma unroll
    for (int i=0;i<4;i++){
        w[i*4+0]=wp[0]; w[i*4+1]=wp[512]; w[i*4+2]=wp[1024]; w[i*4+3]=wp[1536];
        wp += 2048;
    }
}
// 2 row-pairs x 4 gates (P0a)
__device__ __forceinline__ void comp4g2(u64 (&acc)[2][4], const float*& ap, const float (&w)[16]){
    #pragma unroll
    for (int i=0;i<4;i++){
        u64 b0=pk2(w[i*4+0],w[i*4+0]), b1=pk2(w[i*4+1],w[i*4+1]),
            b2=pk2(w[i*4+2],w[i*4+2]), b3=pk2(w[i*4+3],w[i*4+3]);
        u64 a0=((const u64*)ap)[0], a1=((const u64*)ap)[1];
        ap += 36;
        acc[0][0]=ffma2(a0,b0,acc[0][0]); acc[1][0]=ffma2(a1,b0,acc[1][0]);
        acc[0][1]=ffma2(a0,b1,acc[0][1]); acc[1][1]=ffma2(a1,b1,acc[1][1]);
        acc[0][2]=ffma2(a0,b2,acc[0][2]); acc[1][2]=ffma2(a1,b2,acc[1][2]);
        acc[0][3]=ffma2(a0,b3,acc[0][3]); acc[1][3]=ffma2(a1,b3,acc[1][3]);
    }
}

// ================= precompute GEMM (device fn, R12-proven) ====
template<int K, int AMODE, int EPI>
__device__ void dev_g32(float* sm,
    const float* __restrict__ W, const float* __restrict__ Bv,
    const float* __restrict__ A, int lda, int ldw,
    const float* __restrict__ p1, int rowBase, int tt, int colblk)
{
    const int tid = threadIdx.x;
    const int cg  = tid & 63;
    const int rh  = (tid >> 6) & 1;
    const int ks  = tid >> 7;

    for (int idx = tid; idx < 32*K; idx += 256){
        int m = idx / K, k = idx - m*K;
        float v;
        if (AMODE==0) v = A[(size_t)(rowBase+m)*lda + k];
        else          v = (tt==0) ? A[SOSID*512 + k]
                                  : p1[((size_t)m*64 + (tt-1))*512 + k];
        sm[k*36 + m] = v;
    }
    __syncthreads();

    u64 acc[8][4];
    #pragma unroll
    for (int i=0;i<8;i++){ acc[i][0]=0; acc[i][1]=0; acc[i][2]=0; acc[i][3]=0; }

    const float* wp = W + (size_t)(ks*(K/2))*ldw + colblk*256 + cg*4;
    const float* ap = sm + (ks*(K/2))*36 + rh*16;
    const int NT2 = ((K/2)/4)/2;

    float4 wa[4], wb[4];
    load4v(wa, wp, ldw);
    #pragma unroll 1
    for (int j=0;j<NT2-1;j++){
        load4v(wb, wp, ldw);
        comp4v(acc, ap, wa);
        load4v(wa, wp, ldw);
        comp4v(acc, ap, wb);
    }
    load4v(wb, wp, ldw);
    comp4v(acc, ap, wa);
    comp4v(acc, ap, wb);

    __syncthreads();
    u64* red = (u64*)sm;
    u64* mr  = red + (size_t)tid*33;
    #pragma unroll
    for (int m2=0;m2<8;m2++){
        mr[4*m2+0]=acc[m2][0]; mr[4*m2+1]=acc[m2][1];
        mr[4*m2+2]=acc[m2][2]; mr[4*m2+3]=acc[m2][3];
    }
    __syncthreads();
    if (ks == 0){
        const u64* pr = red + (size_t)(tid + 128)*33;
        #pragma unroll
        for (int m2=0;m2<8;m2++){
            acc[m2][0]=fadd2(acc[m2][0],pr[4*m2+0]);
            acc[m2][1]=fadd2(acc[m2][1],pr[4*m2+1]);
            acc[m2][2]=fadd2(acc[m2][2],pr[4*m2+2]);
            acc[m2][3]=fadd2(acc[m2][3],pr[4*m2+3]);
        }
        int c0 = colblk*256 + cg*4;
        #pragma unroll
        for (int m2=0;m2<8;m2++){
            float v0[4], v1[4];
            upk2(acc[m2][0],v0[0],v1[0]); upk2(acc[m2][1],v0[1],v1[1]);
            upk2(acc[m2][2],v0[2],v1[2]); upk2(acc[m2][3],v0[3],v1[3]);
            #pragma unroll
            for (int r=0;r<2;r++){
                int row = rowBase + rh*16 + 2*m2 + r;
                const float* vv = r ? v1 : v0;
                #pragma unroll
                for (int j=0;j<4;j++){
                    int c = c0 + j;
                    float x = vv[j] + Bv[c];
                    if (EPI==0)      g_phi_hs [(size_t)row*512 +c] = tanhf(x);
                    else if (EPI==1) g_phi_fds[(size_t)row*512 +c] = tanhf(x);
                    else             g_zx     [(size_t)row*2048+c] = x;
                }
            }
        }
    }
    __syncthreads();
}

__global__ void __launch_bounds__(256)
pre_all(const float* __restrict__ h0,  const float* __restrict__ c0,
        const float* __restrict__ enc, const float* __restrict__ fld,
        const float* __restrict__ emb, const float* __restrict__ inp,
        const float* __restrict__ lW,  const float* __restrict__ lb,
        const float* __restrict__ Wh,  const float* __restrict__ bh,
        const float* __restrict__ Wf,  const float* __restrict__ bf)
{
    extern __shared__ float sm[];
    const int task = blockIdx.x;
    const int tid  = threadIdx.x;

    if (task < 200){
        dev_g32<512,0,0>(sm, Wh, bh, enc, 512, 512, nullptr, (task>>1)*32, 0, task&1);
    } else if (task < 400){
        int x = task - 200;
        dev_g32<64,0,1>(sm, Wf, bf, fld, 64, 512, nullptr, (x>>1)*32, 0, x&1);
    } else if (task < 920){
        int x = task - 400;
        dev_g32<512,1,2>(sm, lW, lb, emb, 512, 2048, inp, (x>>3)*32, x>>3, x&7);
    } else {
        const int gt = (task-920)*256 + tid, gs = 80*256;
        for (int i=gt; i<16384; i+=gs){ g_hbuf[0][i]=h0[i]; g_cbuf[0][i]=c0[i]; }
        for (int i=gt; i<32*512*104; i+=gs){
            int l=i%104; int hh=(i/104)&511; int b=i/(104*512);
            g_encT[i] = (l<100) ? enc[((size_t)b*100+l)*512+hh] : 0.f;
        }
    }
}

// ================= fused chain kernel (all phases on 128 blocks) ========
__global__ void __launch_bounds__(256, 1)
chain_k(const float* __restrict__ lWh,
        const float* __restrict__ Ws, const float* __restrict__ bs,
        const float* __restrict__ Wr, const float* __restrict__ br,
        const float* __restrict__ Wo, const float* __restrict__ bo,
        const int* __restrict__ lens, int t)
{
    extern __shared__ float sm[];
    const int blk = blockIdx.x;
    const int tid = threadIdx.x;
    const int warp = tid >> 5, lane = tid & 31;
    const int pb = t & 1, cb = pb ^ 1;

    // ---------- P0a: LSTM partials. 128 blocks = 16 h-groups x 8 K-splits ------
    {
        const int hbase = (blk >> 3) * 32;
        const int kq    = blk & 7;
        const int k0    = kq * 64;

        for (int idx = tid; idx < 32*64; idx += 256){
            int m = idx >> 6, k = idx & 63;
            sm[k*36 + m] = g_hbuf[pb][m*512 + k0 + k];
        }
        __syncthreads();

        const int hc = tid & 31;      // coalesced W columns
        const int rg = tid >> 5;      // 8 row-groups x 4 rows

        u64 acc[2][4];
        #pragma unroll
        for (int i=0;i<2;i++){ acc[i][0]=0; acc[i][1]=0; acc[i][2]=0; acc[i][3]=0; }

        const float* wp = lWh + (size_t)k0*2048 + hbase + hc;
        const float* ap = sm + rg*4;

        float wa[16], wb[16];
        load4g(wa, wp);
        #pragma unroll 1
        for (int j=0;j<7;j++){
            load4g(wb, wp);
            comp4g2(acc, ap, wa);
            load4g(wa, wp);
            comp4g2(acc, ap, wb);
        }
        load4g(wb, wp);
        comp4g2(acc, ap, wa);
        comp4g2(acc, ap, wb);

        const int h = hbase + hc;
        #pragma unroll
        for (int p=0;p<2;p++){
            float lo[4], hi[4];
            #pragma unroll
            for (int g=0;g<4;g++) upk2(acc[p][g], lo[g], hi[g]);
            #pragma unroll
            for (int r=0;r<2;r++){
                int b = rg*4 + p*2 + r;
                const float* v = r ? hi : lo;
                #pragma unroll
                for (int g=0;g<4;g++)
                    g_zp[(size_t)(kq*4+g)*16384 + b*512 + h] = v[g];
            }
        }
    }
    gsync();

    // ---------- P0b: gate math + state update (128 elems/block) ----------------
    if (tid < 128){
        int e = blk*128 + tid;
        int b = e >> 9, h = e & 511;
        float vi=0.f, vj=0.f, vf=0.f, vo=0.f;
        #pragma unroll
        for (int ks2=0; ks2<8; ks2++){
            vi += g_zp[(size_t)(ks2*4+0)*16384 + e];
            vj += g_zp[(size_t)(ks2*4+1)*16384 + e];
            vf += g_zp[(size_t)(ks2*4+2)*16384 + e];
            vo += g_zp[(size_t)(ks2*4+3)*16384 + e];
        }
        const float* zxp = g_zx + ((size_t)(t*32+b))*2048 + h;
        vi += zxp[0]; vj += zxp[512]; vf += zxp[1024]; vo += zxp[1536];
        float cp = g_cbuf[pb][e];
        float hp = g_hbuf[pb][e];
        float cn = sigf(vf+1.f)*cp + sigf(vi)*tanhf(vj);
        float hn = sigf(vo)*tanhf(cn);
        bool fin = (t>0) && (t-1 >= lens[b]);
        g_ot[e]       = fin ? 0.f : hn;
        g_hbuf[cb][e] = fin ? hp  : hn;
        g_cbuf[cb][e] = fin ? cp  : cn;
    }
    gsync();

    // ---------- P1: gamma/alpha. 128 blocks x 8 cols, 32-way K split -----------
    {
        for (int idx = tid; idx < 32*512; idx += 256){
            int m = idx >> 9, k = idx & 511;
            sm[k*36 + m] = g_ot[m*512 + k];
        }
        __syncthreads();

        const int dir = blk >> 6;
        const int colbase = (blk & 63) * 8;
        const float* W  = dir ? Wr : Ws;
        const float* Bv = dir ? br : bs;
        float* dst = dir ? g_alpha : g_gamma;

        const int cq = tid & 1;
        const int rq = (tid >> 1) & 3;
        const int ks = tid >> 3;          // 32 splits x 16 k

        u64 acc[4][4];
        #pragma unroll
        for (int i=0;i<4;i++){ acc[i][0]=0; acc[i][1]=0; acc[i][2]=0; acc[i][3]=0; }

        const float* wp = W + (size_t)(ks*16)*512 + colbase + cq*4;
        const float* ap = sm + (ks*16)*36 + rq*8;

        float4 wa[4], wb[4];
        load4v(wa, wp, 512);
        load4v(wb, wp, 512);
        comp4v4(acc, ap, wa);
        load4v(wa, wp, 512);
        comp4v4(acc, ap, wb);
        load4v(wb, wp, 512);
        comp4v4(acc, ap, wa);
        comp4v4(acc, ap, wb);

        __syncthreads();
        u64* red = (u64*)sm;
        u64* mr  = red + (size_t)tid*17;
        #pragma unroll
        for (int m2=0;m2<4;m2++){
            mr[4*m2+0]=acc[m2][0]; mr[4*m2+1]=acc[m2][1];
            mr[4*m2+2]=acc[m2][2]; mr[4*m2+3]=acc[m2][3];
        }
        __syncthreads();
        for (int s=16; s>=1; s>>=1){
            if (ks < s){
                const u64* pr = red + (size_t)(tid + s*8)*17;
                #pragma unroll
                for (int m2=0;m2<4;m2++){
                    acc[m2][0]=fadd2(acc[m2][0],pr[4*m2+0]);
                    acc[m2][1]=fadd2(acc[m2][1],pr[4*m2+1]);
                    acc[m2][2]=fadd2(acc[m2][2],pr[4*m2+2]);
                    acc[m2][3]=fadd2(acc[m2][3],pr[4*m2+3]);
                }
                if (s>1){
                    #pragma unroll
                    for (int m2=0;m2<4;m2++){
                        mr[4*m2+0]=acc[m2][0]; mr[4*m2+1]=acc[m2][1];
                        mr[4*m2+2]=acc[m2][2]; mr[4*m2+3]=acc[m2][3];
                    }
                }
            }
            __syncthreads();
        }
        if (ks == 0){
            const int c0 = colbase + cq*4;
            #pragma unroll
            for (int m2=0;m2<4;m2++){
                float v0[4], v1[4];
                upk2(acc[m2][0],v0[0],v1[0]); upk2(acc[m2][1],v0[1],v1[1]);
                upk2(acc[m2][2],v0[2],v1[2]); upk2(acc[m2][3],v0[3],v1[3]);
                #pragma unroll
                for (int r=0;r<2;r++){
                    int row = rq*8 + 2*m2 + r;
                    const float* vv = r ? v1 : v0;
                    #pragma unroll
                    for (int j=0;j<4;j++){
                        int c = c0 + j;
                        dst[row*512 + c] = tanhf(vv[j] + Bv[c]);
                    }
                }
            }
        }
    }
    gsync();

    // ---------- P2: attention scores, float4 loads, 128 blocks ----------------
    {
        __shared__ float4 sg4[128], sa4[128];
        const int b  = blk & 31;
        const int lq = blk >> 5;
        if (tid < 128){
            sg4[tid] = ((const float4*)(g_gamma + b*512))[tid];
            sa4[tid] = ((const float4*)(g_alpha + b*512))[tid];
        }
        __syncthreads();
        for (int l0 = warp; l0 < 25; l0 += 8){
            int l = lq*25 + l0;
            const float4* ph = (const float4*)(g_phi_hs  + ((size_t)b*100 + l)*512);
            const float4* pf = (const float4*)(g_phi_fds + ((size_t)b*100 + l)*512);
            float s1=0.f, s2=0.f;
            #pragma unroll
            for (int i=0;i<4;i++){
                float4 a = ph[lane + 32*i];
                float4 g = sg4[lane + 32*i];
                s1 += a.x*g.x + a.y*g.y + a.z*g.z + a.w*g.w;
                float4 c = pf[lane + 32*i];
                float4 d = sa4[lane + 32*i];
                s2 += c.x*d.x + c.y*d.y + c.z*d.z + c.w*d.w;
            }
            #pragma unroll
            for (int o=16;o;o>>=1){ s1 += __shfl_xor_sync(~0u,s1,o); s2 += __shfl_xor_sync(~0u,s2,o); }
            if (lane==0){ g_sch[b*100+l]=s1; g_scf[b*100+l]=s2; }
        }
        __syncthreads();
    }
    gsync();

    // ---------- P3: softmaxes + context (4 h-slices/batch) ----------
    {
        __shared__ float sh2[100], sf2[100], sw2[104], aux2[3];
        const int b  = blk >> 2;
        const int hq = blk & 3;
        for (int i = tid; i < 100; i += 256){
            sh2[i] = g_sch[b*100+i];
            sf2[i] = g_scf[b*100+i];
        }
        __syncthreads();
        if (warp < 2){
            float* s = warp ? sf2 : sh2;
            float mx = -1e30f;
            for (int l=lane;l<100;l+=32) mx = fmaxf(mx, s[l]);
            #pragma unroll
            for (int o=16;o;o>>=1) mx = fmaxf(mx, __shfl_xor_sync(~0u,mx,o));
            float sum = 0.f;
            for (int l=lane;l<100;l+=32){ float e = expf(s[l]-mx); s[l]=e; sum+=e; }
            #pragma unroll
            for (int o=16;o;o>>=1) sum += __shfl_xor_sync(~0u,sum,o);
            if (lane==0) aux2[warp] = EPSF + sum;
        }
        __syncthreads();
        if (warp == 0){
            float d1 = aux2[0], d2 = aux2[1];
            float wsum = 0.f;
            for (int l=lane;l<100;l+=32){ float w = (sh2[l]/d1)*(sf2[l]/d2); sw2[l]=w; wsum += w; }
            #pragma unroll
            for (int o=16;o;o>>=1) wsum += __shfl_xor_sync(~0u,wsum,o);
            if (lane==0) aux2[2] = EPSF + wsum;
        }
        __syncthreads();
        if (warp == 0){
            float d = aux2[2];
            for (int l=lane;l<100;l+=32) sw2[l] = sw2[l]/d;
            if (lane < 4) sw2[100+lane] = 0.f;
        }
        __syncthreads();
        if (tid < 128){
            int h = hq*128 + tid;
            const float4* e = (const float4*)(g_encT + ((size_t)b*512 + h)*104);
            float c2 = 0.f;
            #pragma unroll
            for (int l4=0; l4<26; l4++){
                float4 ev = e[l4];
                int l = l4*4;
                c2 += sw2[l+0]*ev.x + sw2[l+1]*ev.y + sw2[l+2]*ev.z + sw2[l+3]*ev.w;
            }
            g_ctx[b*512+h] = c2;
        }
        __syncthreads();
    }
    gsync();

    // ---------- P4: att(t). 128 blocks x 4 cols, K=1024, 64-way K split --------
    {
        for (int idx = tid; idx < 32*1024; idx += 256){
            int m = idx >> 10, k = idx & 1023;
            float v = (k < 512) ? g_ctx[m*512+k] : g_ot[m*512+k-512];
            sm[k*36 + m] = v;
        }
        __syncthreads();

        const int colbase = blk * 4;
        const int rq = tid & 3;
        const int ks = tid >> 2;          // 64 splits x 16 k

        u64 acc[4][4];
        #pragma unroll
        for (int i=0;i<4;i++){ acc[i][0]=0; acc[i][1]=0; acc[i][2]=0; acc[i][3]=0; }

        const float* wp = Wo + (size_t)(ks*16)*512 + colbase;
        const float* ap = sm + (ks*16)*36 + rq*8;

        float4 wa[4], wb[4];
        load4v(wa, wp, 512);
        load4v(wb, wp, 512);
        comp4v4(acc, ap, wa);
        load4v(wa, wp, 512);
        comp4v4(acc, ap, wb);
        load4v(wb, wp, 512);
        comp4v4(acc, ap, wa);
        comp4v4(acc, ap, wb);

        __syncthreads();
        u64* red = (u64*)sm;
        u64* mr  = red + (size_t)tid*17;
        #pragma unroll
        for (int m2=0;m2<4;m2++){
            mr[4*m2+0]=acc[m2][0]; mr[4*m2+1]=acc[m2][1];
            mr[4*m2+2]=acc[m2][2]; mr[4*m2+3]=acc[m2][3];
        }
        __syncthreads();
        for (int s=32; s>=1; s>>=1){
            if (ks < s){
                const u64* pr = red + (size_t)(tid + s*4)*17;
                #pragma unroll
                for (int m2=0;m2<4;m2++){
                    acc[m2][0]=fadd2(acc[m2][0],pr[4*m2+0]);
                    acc[m2][1]=fadd2(acc[m2][1],pr[4*m2+1]);
                    acc[m2][2]=fadd2(acc[m2][2],pr[4*m2+2]);
                    acc[m2][3]=fadd2(acc[m2][3],pr[4*m2+3]);
                }
                if (s>1){
                    #pragma unroll
                    for (int m2=0;m2<4;m2++){
                        mr[4*m2+0]=acc[m2][0]; mr[4*m2+1]=acc[m2][1];
                        mr[4*m2+2]=acc[m2][2]; mr[4*m2+3]=acc[m2][3];
                    }
                }
            }
            __syncthreads();
        }
        if (ks == 0){
            float* dst = g_att_all + (size_t)t*16384;
            #pragma unroll
            for (int m2=0;m2<4;m2++){
                float v0[4], v1[4];
                upk2(acc[m2][0],v0[0],v1[0]); upk2(acc[m2][1],v0[1],v1[1]);
                upk2(acc[m2][2],v0[2],v1[2]); upk2(acc[m2][3],v0[3],v1[3]);
                #pragma unroll
                for (int r=0;r<2;r++){
                    int row = rq*8 + 2*m2 + r;
                    bool fin = (t>0) && (t-1 >= lens[row]);
                    const float* vv = r ? v1 : v0;
                    #pragma unroll
                    for (int j=0;j<4;j++){
                        int c = colbase + j;
                        float v = tanhf(vv[j] + bo[c]);
                        dst[row*512 + c] = fin ? 0.f : v;
                    }
                }
            }
        }
    }
}

// ---- logits chunk: grid 250 x 256; 128 cols/block for nt steps (R14-proven) --
__global__ void __launch_bounds__(256)
logits_chunk(const float* __restrict__ oW, const float* __restrict__ ob,
             const int* __restrict__ lens, float* __restrict__ out, int t0, int nt)
{
    extern __shared__ float sm[];
    const int tid = threadIdx.x, blk = blockIdx.x;
    const int cg = tid & 31;
    const int rh = (tid >> 5) & 1;
    const int ks = tid >> 6;

    for (int tt = t0; tt < t0 + nt; tt++){
        const float* attb = g_att_all + (size_t)tt*16384;
        __syncthreads();
        for (int idx = tid; idx < 32*512; idx += 256){
            int m = idx >> 9, k = idx & 511;
            sm[k*36 + m] = attb[m*512 + k];
        }
        __syncthreads();

        u64 acc[8][4];
        #pragma unroll
        for (int i=0;i<8;i++){ acc[i][0]=0; acc[i][1]=0; acc[i][2]=0; acc[i][3]=0; }

        const float* wp = oW + (size_t)(ks*128)*32000 + blk*128 + cg*4;
        const float* ap = sm + (ks*128)*36 + rh*16;

        float4 wa[4], wb[4];
        load4v(wa, wp, 32000);
        #pragma unroll 1
        for (int j=0;j<15;j++){
            load4v(wb, wp, 32000);
            comp4v(acc, ap, wa);
            load4v(wa, wp, 32000);
            comp4v(acc, ap, wb);
        }
        load4v(wb, wp, 32000);
        comp4v(acc, ap, wa);
        comp4v(acc, ap, wb);

        __syncthreads();
        u64* red = (u64*)sm;
        u64* mr  = red + (size_t)tid*33;
        #pragma unroll
        for (int m2=0;m2<8;m2++){
            mr[4*m2+0]=acc[m2][0]; mr[4*m2+1]=acc[m2][1];
            mr[4*m2+2]=acc[m2][2]; mr[4*m2+3]=acc[m2][3];
        }
        __syncthreads();
        for (int s=2; s>=1; s>>=1){
            if (ks < s){
                const u64* pr = red + (size_t)(tid + s*64)*33;
                #pragma unroll
                for (int m2=0;m2<8;m2++){
                    acc[m2][0]=fadd2(acc[m2][0],pr[4*m2+0]);
                    acc[m2][1]=fadd2(acc[m2][1],pr[4*m2+1]);
                    acc[m2][2]=fadd2(acc[m2][2],pr[4*m2+2]);
                    acc[m2][3]=fadd2(acc[m2][3],pr[4*m2+3]);
                }
                if (s>1){
                    #pragma unroll
                    for (int m2=0;m2<8;m2++){
                        mr[4*m2+0]=acc[m2][0]; mr[4*m2+1]=acc[m2][1];
                        mr[4*m2+2]=acc[m2][2]; mr[4*m2+3]=acc[m2][3];
                    }
                }
            }
            __syncthreads();
        }
        if (ks == 0){
            const int c0 = blk*128 + cg*4;
            #pragma unroll
            for (int m2=0;m2<8;m2++){
                float v0[4], v1[4];
                upk2(acc[m2][0],v0[0],v1[0]); upk2(acc[m2][1],v0[1],v1[1]);
                upk2(acc[m2][2],v0[2],v1[2]); upk2(acc[m2][3],v0[3],v1[3]);
                #pragma unroll
                for (int r=0;r<2;r++){
                    int row = rh*16 + 2*m2 + r;
                    bool fin = (tt>0) && (tt-1 >= lens[row]);
                    const float* vv = r ? v1 : v0;
                    float* op = out + (size_t)row*2080000 + (size_t)tt*32000 + c0;
                    #pragma unroll
                    for (int j=0;j<4;j++)
                        op[j] = fin ? 0.f : (vv[j] + ob[c0+j]);
                }
            }
        }
    }
}

// ---- final h/c ----
__global__ void fin_k(float* __restrict__ out)
{
    int i = blockIdx.x*256 + threadIdx.x;
    if (i < 16384){
        out[66560000 + i]         = g_hbuf[1][i];
        out[66560000 + 16384 + i] = g_cbuf[1][i];
    }
}

// ---------------- host ----------------
extern "C" void kernel_launch(void* const* d_in, const int* in_sizes, int n_in,
                              void* d_out, int out_size)
{
    const float* h0   = (const float*)d_in[0];
    const float* c0   = (const float*)d_in[1];
    const float* inp  = (const float*)d_in[2];
    const float* enc  = (const float*)d_in[3];
    const float* fld  = (const float*)d_in[4];
    const float* emb  = (const float*)d_in[5];
    const float* lW   = (const float*)d_in[6];
    const float* lb   = (const float*)d_in[7];
    const float* Wh   = (const float*)d_in[8];
    const float* bh   = (const float*)d_in[9];
    const float* Ws   = (const float*)d_in[10];
    const float* bs   = (const float*)d_in[11];
    const float* Wr   = (const float*)d_in[12];
    const float* br   = (const float*)d_in[13];
    const float* Wf   = (const float*)d_in[14];
    const float* bf   = (const float*)d_in[15];
    const float* Wo   = (const float*)d_in[16];
    const float* bo   = (const float*)d_in[17];
    const float* oW   = (const float*)d_in[18];
    const float* ob   = (const float*)d_in[19];
    const int*   lens = (const int*)  d_in[20];
    float* out = (float*)d_out;

    const int SM_PRE   = 512*36*4;      // 73728
    const int SM_CHAIN = 1024*36*4;     // 147456
    const int SM_LOG   = 512*36*4;      // 73728

    cudaFuncSetAttribute((const void*)pre_all,      cudaFuncAttributeMaxDynamicSharedMemorySize, SM_PRE);
    cudaFuncSetAttribute((const void*)chain_k,      cudaFuncAttributeMaxDynamicSharedMemorySize, SM_CHAIN);
    cudaFuncSetAttribute((const void*)logits_chunk, cudaFuncAttributeMaxDynamicSharedMemorySize, SM_LOG);

    cudaStream_t s2;
    cudaStreamCreateWithFlags(&s2, cudaStreamNonBlocking);
    cudaEvent_t eC[5], eJ;
    for (int i=0;i<5;i++) cudaEventCreateWithFlags(&eC[i], cudaEventDisableTiming);
    cudaEventCreateWithFlags(&eJ, cudaEventDisableTiming);

    pre_all<<<1000, 256, SM_PRE>>>(h0, c0, enc, fld, emb, inp, lW, lb,
                                   Wh, bh, Wf, bf);

    const float* lWh = lW + (size_t)512*2048;
    const int chunk_end[5] = {15, 31, 47, 63, 64};
    const int chunk_t0[5]  = {0, 16, 32, 48, 64};
    const int chunk_nt[5]  = {16, 16, 16, 16, 1};
    int ci = 0;

    for (int t = 0; t < 65; t++){
        chain_k<<<128, 256, SM_CHAIN>>>(lWh, Ws, bs, Wr, br, Wo, bo, lens, t);
        if (ci < 5 && t == chunk_end[ci]){
            cudaEventRecord(eC[ci], 0);
            cudaStreamWaitEvent(s2, eC[ci], 0);
            logits_chunk<<<250, 256, SM_LOG, s2>>>(oW, ob, lens, out,
                                                   chunk_t0[ci], chunk_nt[ci]);
            ci++;
        }
    }
    cudaEventRecord(eJ, s2);
    cudaStreamWaitEvent(0, eJ, 0);
    fin_k<<<64, 256>>>(out);

    (void)in_sizes; (void)n_in; (void)out_size;
}